// round 1
// baseline (speedup 1.0000x reference)
#include <cuda_runtime.h>
#include <math.h>

#define BATCH 1024
#define NMEM  400
#define DDIM  3
#define HDIM  256
#define NH    4
#define DHD   64

// ---------------- scratch (no allocation allowed) ----------------
__device__ float g_bufA[BATCH*HDIM];
__device__ float g_bufB[BATCH*HDIM];
__device__ float g_ctx [BATCH*HDIM];
__device__ float g_base[BATCH*NMEM];
__device__ float g_me  [NMEM*HDIM];
__device__ float g_k   [NMEM*HDIM];
__device__ float g_v   [NMEM*HDIM];
__device__ float g_q   [BATCH*HDIM];
__device__ float g_scores[BATCH*NH*NMEM];
__device__ float g_att [BATCH*HDIM];
__device__ float g_attd[BATCH*HDIM];
__device__ float g_attw[BATCH*NMEM];
__device__ float g_div [BATCH];

__device__ __forceinline__ float gelu_exact(float x) {
    return 0.5f * x * (1.0f + erff(x * 0.70710678118654752440f));
}

// =================================================================
// Row-fused GEMM: C[rows x 256] = act(LN(A[rows x K] @ W[K x 256] + bias))
// BM=8 rows per block, full 256-col row in one block so LN can fuse.
// 256 threads: tx = tid&63 (4 cols each), ty = tid>>6 (rows ty, ty+4).
// =================================================================
template<bool CONCAT, bool DO_LN, bool DO_GELU, int KIT>
__global__ __launch_bounds__(256)
void fused_row_gemm(const float* __restrict__ A,
                    const float* __restrict__ mf,      // CONCAT only
                    const float* __restrict__ regtab,  // CONCAT only
                    const int*   __restrict__ rid,     // CONCAT only
                    const float* __restrict__ W,       // [K][256]
                    const float* __restrict__ bias,    // [256]
                    const float* __restrict__ ln_g,
                    const float* __restrict__ ln_b,
                    float* __restrict__ Cout)
{
    __shared__ float As[32][8];
    __shared__ float Bs[32 * 256];
    __shared__ float red1[8 * 64];
    __shared__ float red2[8 * 64];
    __shared__ float2 stats[8];

    const int tid = threadIdx.x;
    const int tx = tid & 63, ty = tid >> 6;
    const int rowBase = blockIdx.x * 8;
    const int K = KIT * 32;

    float acc[2][4] = {};

    for (int kt = 0; kt < KIT; kt++) {
        // ---- load A tile (8 rows x 32 k), store transposed+permuted ----
        {
            int r  = tid >> 5;
            int kk = tid & 31;
            int gk = kt * 32 + kk;
            int grow = rowBase + r;
            float av;
            if constexpr (CONCAT) {
                av = (gk < 128) ? mf[grow * 128 + gk]
                                : regtab[rid[grow] * 32 + (gk - 128)];
            } else {
                av = A[grow * K + gk];
            }
            As[kk][(r & 3) * 2 + (r >> 2)] = av;
        }
        // ---- load B tile (32 x 256) linearly as float4 ----
        {
            const float4* Wg  = (const float4*)(W + kt * 32 * 256);
            float4*       Bs4 = (float4*)Bs;
#pragma unroll
            for (int j = 0; j < 8; j++) {
                int idx = tid + j * 256;
                Bs4[idx] = Wg[idx];
            }
        }
        __syncthreads();
#pragma unroll
        for (int kk = 0; kk < 32; kk++) {
            float2 a = *(const float2*)&As[kk][ty * 2];
            float4 b = *(const float4*)&Bs[kk * 256 + tx * 4];
            acc[0][0] += a.x * b.x; acc[0][1] += a.x * b.y;
            acc[0][2] += a.x * b.z; acc[0][3] += a.x * b.w;
            acc[1][0] += a.y * b.x; acc[1][1] += a.y * b.y;
            acc[1][2] += a.y * b.z; acc[1][3] += a.y * b.w;
        }
        __syncthreads();
    }

    // bias
    float4 bv = *(const float4*)&bias[tx * 4];
    float x[2][4];
#pragma unroll
    for (int i = 0; i < 2; i++) {
        x[i][0] = acc[i][0] + bv.x;
        x[i][1] = acc[i][1] + bv.y;
        x[i][2] = acc[i][2] + bv.z;
        x[i][3] = acc[i][3] + bv.w;
    }

    if constexpr (DO_LN) {
#pragma unroll
        for (int i = 0; i < 2; i++) {
            int r = ty + 4 * i;
            float s1 = x[i][0] + x[i][1] + x[i][2] + x[i][3];
            float s2 = x[i][0]*x[i][0] + x[i][1]*x[i][1]
                     + x[i][2]*x[i][2] + x[i][3]*x[i][3];
            red1[r * 64 + tx] = s1;
            red2[r * 64 + tx] = s2;
        }
        __syncthreads();
        if (tid < 8) {
            float s1 = 0.f, s2 = 0.f;
            for (int t = 0; t < 64; t++) { s1 += red1[tid*64 + t]; s2 += red2[tid*64 + t]; }
            float mean = s1 * (1.0f / 256.0f);
            float var  = s2 * (1.0f / 256.0f) - mean * mean;
            stats[tid] = make_float2(mean, rsqrtf(var + 1e-5f));
        }
        __syncthreads();
        float4 gv = *(const float4*)&ln_g[tx * 4];
        float4 bb = *(const float4*)&ln_b[tx * 4];
#pragma unroll
        for (int i = 0; i < 2; i++) {
            float2 st = stats[ty + 4 * i];
            x[i][0] = (x[i][0] - st.x) * st.y * gv.x + bb.x;
            x[i][1] = (x[i][1] - st.x) * st.y * gv.y + bb.y;
            x[i][2] = (x[i][2] - st.x) * st.y * gv.z + bb.z;
            x[i][3] = (x[i][3] - st.x) * st.y * gv.w + bb.w;
        }
    }

    if constexpr (DO_GELU) {
#pragma unroll
        for (int i = 0; i < 2; i++)
#pragma unroll
            for (int j = 0; j < 4; j++)
                x[i][j] = gelu_exact(x[i][j]);
    }

#pragma unroll
    for (int i = 0; i < 2; i++) {
        int grow = rowBase + ty + 4 * i;
        *(float4*)&Cout[grow * 256 + tx * 4] =
            make_float4(x[i][0], x[i][1], x[i][2], x[i][3]);
    }
}

// =================================================================
// Generic tiled GEMM: C = scale * (A @ opB(B)) [+ bias]
// 64x64 tiles, BK=32, 256 threads, 4x4 register tile.
// z dimension applies per-head element offsets.
// =================================================================
template<bool OPB_T, bool BIAS>
__global__ __launch_bounds__(256)
void gemm_plain(const float* __restrict__ A, int lda, int aoz,
                const float* __restrict__ Bm, int ldb, int boz,
                const float* __restrict__ bias,
                float* __restrict__ Cm, int ldc, int coz,
                int Md, int Nd, int Kd, float scale)
{
    __shared__ float As[32][65];
    __shared__ float Bs[32][65];

    const int tid = threadIdx.x;
    const int tx = tid & 15, ty = tid >> 4;
    const int bm = blockIdx.y * 64, bn = blockIdx.x * 64;
    const int z = blockIdx.z;
    A  += (long)z * aoz;
    Bm += (long)z * boz;
    Cm += (long)z * coz;

    float acc[4][4] = {};

    for (int kt = 0; kt < Kd; kt += 32) {
#pragma unroll
        for (int j = 0; j < 8; j++) {
            int idx = tid + j * 256;
            int r = idx >> 5, kk = idx & 31;
            int gr = bm + r, gk = kt + kk;
            As[kk][r] = (gr < Md && gk < Kd) ? A[gr * lda + gk] : 0.f;
        }
#pragma unroll
        for (int j = 0; j < 8; j++) {
            int idx = tid + j * 256;
            if (OPB_T) {
                int n = idx >> 5, kk = idx & 31;
                int gn = bn + n, gk = kt + kk;
                Bs[kk][n] = (gn < Nd && gk < Kd) ? Bm[gn * ldb + gk] : 0.f;
            } else {
                int kk = idx >> 6, n = idx & 63;
                int gn = bn + n, gk = kt + kk;
                Bs[kk][n] = (gn < Nd && gk < Kd) ? Bm[gk * ldb + gn] : 0.f;
            }
        }
        __syncthreads();
#pragma unroll
        for (int kk = 0; kk < 32; kk++) {
            float a[4], b[4];
#pragma unroll
            for (int i = 0; i < 4; i++) a[i] = As[kk][ty * 4 + i];
#pragma unroll
            for (int j = 0; j < 4; j++) b[j] = Bs[kk][tx * 4 + j];
#pragma unroll
            for (int i = 0; i < 4; i++)
#pragma unroll
                for (int j = 0; j < 4; j++)
                    acc[i][j] += a[i] * b[j];
        }
        __syncthreads();
    }

#pragma unroll
    for (int i = 0; i < 4; i++) {
        int gr = bm + ty * 4 + i;
        if (gr >= Md) continue;
#pragma unroll
        for (int j = 0; j < 4; j++) {
            int gc = bn + tx * 4 + j;
            if (gc < Nd) {
                float v = acc[i][j] * scale;
                if (BIAS) v += bias[gc];
                Cm[gr * ldc + gc] = v;
            }
        }
    }
}

// =================================================================
// Softmax over rows of length 400 (scores), 128 threads / row
// =================================================================
__global__ __launch_bounds__(128)
void softmax_rows(float* __restrict__ s)
{
    __shared__ float sm[128];
    int row = blockIdx.x;
    float* p = s + (long)row * 400;
    int tid = threadIdx.x;

    float v[4];
    float mx = -1e30f;
#pragma unroll
    for (int i = 0; i < 4; i++) {
        int m = tid + i * 128;
        v[i] = (m < 400) ? p[m] : -1e30f;
        mx = fmaxf(mx, v[i]);
    }
    sm[tid] = mx; __syncthreads();
    for (int st = 64; st > 0; st >>= 1) {
        if (tid < st) sm[tid] = fmaxf(sm[tid], sm[tid + st]);
        __syncthreads();
    }
    mx = sm[0]; __syncthreads();

    float e[4]; float sum = 0.f;
#pragma unroll
    for (int i = 0; i < 4; i++) {
        int m = tid + i * 128;
        e[i] = (m < 400) ? expf(v[i] - mx) : 0.f;
        sum += e[i];
    }
    sm[tid] = sum; __syncthreads();
    for (int st = 64; st > 0; st >>= 1) {
        if (tid < st) sm[tid] += sm[tid + st];
        __syncthreads();
    }
    float inv = 1.0f / sm[0];
#pragma unroll
    for (int i = 0; i < 4; i++) {
        int m = tid + i * 128;
        if (m < 400) p[m] = e[i] * inv;
    }
}

// ---------------- block reductions (128 threads) ----------------
__device__ __forceinline__ float bredSum(float v, float* sm)
{
    int tid = threadIdx.x;
    __syncthreads();
    sm[tid] = v; __syncthreads();
    for (int st = 64; st > 0; st >>= 1) {
        if (tid < st) sm[tid] += sm[tid + st];
        __syncthreads();
    }
    return sm[0];
}
__device__ __forceinline__ float bredMax(float v, float* sm)
{
    int tid = threadIdx.x;
    __syncthreads();
    sm[tid] = v; __syncthreads();
    for (int st = 64; st > 0; st >>= 1) {
        if (tid < st) sm[tid] = fmaxf(sm[tid], sm[tid + st]);
        __syncthreads();
    }
    return sm[0];
}

// =================================================================
// Combine: logits -> softmax -> clip -> renorm -> w, prediction,
// per-batch diversity partial
// =================================================================
__global__ __launch_bounds__(128)
void combine_kernel(const float* __restrict__ base,
                    const float* __restrict__ attw,
                    const float* __restrict__ mp,
                    float* __restrict__ out_pred,
                    float* __restrict__ out_w,
                    float* __restrict__ divp)
{
    __shared__ float sm[128];
    int b = blockIdx.x, tid = threadIdx.x;
    const float* bp = base + (long)b * 400;
    const float* ap = attw + (long)b * 400;

    float l[4];
    float mx = -1e30f;
#pragma unroll
    for (int i = 0; i < 4; i++) {
        int m = tid + i * 128;
        if (m < 400) { l[i] = bp[m] + 0.5f * ap[m]; mx = fmaxf(mx, l[i]); }
        else l[i] = -1e30f;
    }
    mx = bredMax(mx, sm);

    float e[4]; float s = 0.f;
#pragma unroll
    for (int i = 0; i < 4; i++) {
        int m = tid + i * 128;
        e[i] = (m < 400) ? expf(l[i] - mx) : 0.f;
        s += e[i];
    }
    s = bredSum(s, sm);
    float invs = 1.0f / s;

    float w1[4]; float s2 = 0.f;
#pragma unroll
    for (int i = 0; i < 4; i++) {
        int m = tid + i * 128;
        w1[i] = (m < 400) ? fmaxf(e[i] * invs, 0.001f) : 0.f;
        s2 += w1[i];
    }
    s2 = bredSum(s2, sm);
    float inv2 = 1.0f / s2;

    float p0 = 0.f, p1 = 0.f, p2 = 0.f;
    float sx = 0.f, sy = 0.f, sz = 0.f, tt = 0.f;
#pragma unroll
    for (int i = 0; i < 4; i++) {
        int m = tid + i * 128;
        if (m < 400) {
            float w = w1[i] * inv2;
            out_w[(long)b * 400 + m] = w;
            const float* row = mp + ((long)b * 400 + m) * 3;
            float x0 = row[0], x1 = row[1], x2 = row[2];
            p0 += w * x0; p1 += w * x1; p2 += w * x2;
            float n2 = x0*x0 + x1*x1 + x2*x2;
            float nr = fmaxf(sqrtf(n2), 1e-12f);
            float invn = 1.0f / nr;
            sx += x0 * invn; sy += x1 * invn; sz += x2 * invn;
            tt += n2 * invn * invn;
        }
    }
    p0 = bredSum(p0, sm); p1 = bredSum(p1, sm); p2 = bredSum(p2, sm);
    sx = bredSum(sx, sm); sy = bredSum(sy, sm); sz = bredSum(sz, sm);
    tt = bredSum(tt, sm);
    if (tid == 0) {
        out_pred[b * 3 + 0] = p0;
        out_pred[b * 3 + 1] = p1;
        out_pred[b * 3 + 2] = p2;
        divp[b] = sx*sx + sy*sy + sz*sz - tt;
    }
}

__global__ __launch_bounds__(256)
void final_div(const float* __restrict__ divp, float* __restrict__ outp)
{
    __shared__ float sm[256];
    int tid = threadIdx.x;
    float s = 0.f;
    for (int i = tid; i < 1024; i += 256) s += divp[i];
    sm[tid] = s; __syncthreads();
    for (int st = 128; st > 0; st >>= 1) {
        if (tid < st) sm[tid] += sm[tid + st];
        __syncthreads();
    }
    if (tid == 0)
        outp[0] = sm[0] / (1024.0f * 400.0f * 399.0f) * 0.1f;
}

// =================================================================
extern "C" void kernel_launch(void* const* d_in, const int* in_sizes, int n_in,
                              void* d_out, int out_size)
{
    const float* mf     = (const float*)d_in[0];
    const float* mp     = (const float*)d_in[1];
    const float* regtab = (const float*)d_in[2];
    const float* enc_w1 = (const float*)d_in[3];
    const float* enc_b1 = (const float*)d_in[4];
    const float* ln1g   = (const float*)d_in[5];
    const float* ln1b   = (const float*)d_in[6];
    const float* enc_w2 = (const float*)d_in[7];
    const float* enc_b2 = (const float*)d_in[8];
    const float* ln2g   = (const float*)d_in[9];
    const float* ln2b   = (const float*)d_in[10];
    const float* enc_w3 = (const float*)d_in[11];
    const float* enc_b3 = (const float*)d_in[12];
    const float* wg_w1  = (const float*)d_in[13];
    const float* wg_b1  = (const float*)d_in[14];
    const float* wg_w2  = (const float*)d_in[15];
    const float* wg_b2  = (const float*)d_in[16];
    const float* wg_w3  = (const float*)d_in[17];
    const float* wg_b3  = (const float*)d_in[18];
    const float* memb   = (const float*)d_in[19];
    const float* proj_w = (const float*)d_in[20];
    const float* proj_b = (const float*)d_in[21];
    const float* wq     = (const float*)d_in[22];
    const float* bq     = (const float*)d_in[23];
    const float* wk     = (const float*)d_in[24];
    const float* bk     = (const float*)d_in[25];
    const float* wv     = (const float*)d_in[26];
    const float* bv     = (const float*)d_in[27];
    const float* wo     = (const float*)d_in[28];
    const float* bo     = (const float*)d_in[29];
    const int*   rid    = (const int*)d_in[30];
    float* out = (float*)d_out;

    float *bufA, *bufB, *ctx, *base, *me, *kb, *vb, *qb, *sc, *att, *attd, *attwp, *divp;
    cudaGetSymbolAddress((void**)&bufA,  g_bufA);
    cudaGetSymbolAddress((void**)&bufB,  g_bufB);
    cudaGetSymbolAddress((void**)&ctx,   g_ctx);
    cudaGetSymbolAddress((void**)&base,  g_base);
    cudaGetSymbolAddress((void**)&me,    g_me);
    cudaGetSymbolAddress((void**)&kb,    g_k);
    cudaGetSymbolAddress((void**)&vb,    g_v);
    cudaGetSymbolAddress((void**)&qb,    g_q);
    cudaGetSymbolAddress((void**)&sc,    g_scores);
    cudaGetSymbolAddress((void**)&att,   g_att);
    cudaGetSymbolAddress((void**)&attd,  g_attd);
    cudaGetSymbolAddress((void**)&attwp, g_attw);
    cudaGetSymbolAddress((void**)&divp,  g_div);

    // ---- encoder ----
    fused_row_gemm<true,  true,  true, 5><<<128, 256>>>(nullptr, mf, regtab, rid,
                                                        enc_w1, enc_b1, ln1g, ln1b, bufA);
    fused_row_gemm<false, true,  true, 8><<<128, 256>>>(bufA, nullptr, nullptr, nullptr,
                                                        enc_w2, enc_b2, ln2g, ln2b, bufB);
    fused_row_gemm<false, false, false,8><<<128, 256>>>(bufB, nullptr, nullptr, nullptr,
                                                        enc_w3, enc_b3, nullptr, nullptr, ctx);
    // ---- hypernet base weights ----
    fused_row_gemm<false, false, true, 8><<<128, 256>>>(ctx,  nullptr, nullptr, nullptr,
                                                        wg_w1, wg_b1, nullptr, nullptr, bufA);
    fused_row_gemm<false, false, true, 8><<<128, 256>>>(bufA, nullptr, nullptr, nullptr,
                                                        wg_w2, wg_b2, nullptr, nullptr, bufB);
    gemm_plain<false, true><<<dim3(7, 16, 1), 256>>>(bufB, 256, 0, wg_w3, 400, 0, wg_b3,
                                                     base, 400, 0, 1024, 400, 256, 1.0f);
    // ---- member attention ----
    fused_row_gemm<false, false, false,2><<<50, 256>>>(memb, nullptr, nullptr, nullptr,
                                                       proj_w, proj_b, nullptr, nullptr, me);
    fused_row_gemm<false, false, false,8><<<50, 256>>>(me, nullptr, nullptr, nullptr,
                                                       wk, bk, nullptr, nullptr, kb);
    fused_row_gemm<false, false, false,8><<<50, 256>>>(me, nullptr, nullptr, nullptr,
                                                       wv, bv, nullptr, nullptr, vb);
    fused_row_gemm<false, false, false,8><<<128, 256>>>(ctx, nullptr, nullptr, nullptr,
                                                        wq, bq, nullptr, nullptr, qb);
    // scores[b,h,m] = q_h . k_h / 8
    gemm_plain<true, false><<<dim3(7, 16, 4), 256>>>(qb, 256, 64, kb, 256, 64, nullptr,
                                                     sc, 1600, 400, 1024, 400, 64, 0.125f);
    softmax_rows<<<4096, 128>>>(sc);
    // att[b, h*64+d] = a . v_h
    gemm_plain<false, false><<<dim3(1, 16, 4), 256>>>(sc, 1600, 400, vb, 256, 64, nullptr,
                                                      att, 256, 64, 1024, 64, 400, 1.0f);
    fused_row_gemm<false, false, false,8><<<128, 256>>>(att, nullptr, nullptr, nullptr,
                                                        wo, bo, nullptr, nullptr, attd);
    // attention_weights = attended @ me^T
    gemm_plain<true, false><<<dim3(7, 16, 1), 256>>>(attd, 256, 0, me, 256, 0, nullptr,
                                                     attwp, 400, 0, 1024, 400, 256, 1.0f);
    // ---- combine + prediction + diversity ----
    combine_kernel<<<1024, 128>>>(base, attwp, mp, out, out + 3072, divp);
    final_div<<<1, 256>>>(divp, out + 412672);
}

// round 2
// speedup vs baseline: 1.3657x; 1.3657x over previous
#include <cuda_runtime.h>
#include <math.h>

// ---------------- scratch (no allocation allowed) ----------------
__device__ float g_meT[256 * 400];   // me transposed [k][m]
__device__ float g_kT [256 * 400];   // k transposed  [dfull][m]
__device__ float g_v  [400 * 256];   // v normal      [m][dfull]
__device__ float g_div[1024];

__device__ __forceinline__ float gelu_exact(float x) {
    return 0.5f * x * (1.0f + erff(x * 0.70710678118654752440f));
}

// =================================================================
// prep kernel: me = memb@proj_w+b ; k = me@wk+bk ; v = me@wv+bv
// 100 blocks x 256 threads, 4 member-rows per block.
// thread t owns output column t; x in smem k-major [k][4 rows].
// =================================================================
__device__ __forceinline__ void gemm4(const float* __restrict__ W,
                                      const float* __restrict__ xs,
                                      float acc[4], int K, int t)
{
    float w[8];
#pragma unroll
    for (int u = 0; u < 8; u++) w[u] = W[u * 256 + t];
    for (int k0 = 0; k0 < K; k0 += 8) {
        float wn[8];
        bool more = (k0 + 8) < K;
#pragma unroll
        for (int u = 0; u < 8; u++) wn[u] = more ? W[(k0 + 8 + u) * 256 + t] : 0.f;
#pragma unroll
        for (int u = 0; u < 8; u++) {
            float4 xa = *(const float4*)&xs[(k0 + u) * 4];
            acc[0] += xa.x * w[u]; acc[1] += xa.y * w[u];
            acc[2] += xa.z * w[u]; acc[3] += xa.w * w[u];
        }
#pragma unroll
        for (int u = 0; u < 8; u++) w[u] = wn[u];
    }
}

__global__ __launch_bounds__(256)
void prep_kernel(const float* __restrict__ memb,
                 const float* __restrict__ proj_w, const float* __restrict__ proj_b,
                 const float* __restrict__ wk, const float* __restrict__ bk,
                 const float* __restrict__ wv, const float* __restrict__ bv,
                 float* __restrict__ meT, float* __restrict__ kT, float* __restrict__ v)
{
    __shared__ float xm[64 * 4];
    __shared__ float mes[256 * 4];
    const int t = threadIdx.x;
    const int g0 = blockIdx.x * 4;

    {   // load memb rows [4][64] -> k-major
        int r = t >> 6, k = t & 63;
        xm[k * 4 + r] = memb[(g0 + r) * 64 + k];
    }
    __syncthreads();

    float me[4];
    { float b = proj_b[t]; me[0] = me[1] = me[2] = me[3] = b; }
    gemm4(proj_w, xm, me, 64, t);
#pragma unroll
    for (int r = 0; r < 4; r++) mes[t * 4 + r] = me[r];
    *(float4*)&meT[t * 400 + g0] = make_float4(me[0], me[1], me[2], me[3]);
    __syncthreads();

    float ak[4];
    { float b = bk[t]; ak[0] = ak[1] = ak[2] = ak[3] = b; }
    gemm4(wk, mes, ak, 256, t);
    *(float4*)&kT[t * 400 + g0] = make_float4(ak[0], ak[1], ak[2], ak[3]);

    float av[4];
    { float b = bv[t]; av[0] = av[1] = av[2] = av[3] = b; }
    gemm4(wv, mes, av, 256, t);
#pragma unroll
    for (int r = 0; r < 4; r++) v[(g0 + r) * 256 + t] = av[r];
}

// =================================================================
// mega kernel helpers (8 rows per block, 256 threads)
// =================================================================

// acc[8] += sum_k xs[k][0..7] * W[k*256 + t]   (prefetch-pipelined)
__device__ __forceinline__ void gemm8(const float* __restrict__ W,
                                      const float* __restrict__ xs,
                                      float acc[8], int K, int t)
{
    float w[8];
#pragma unroll
    for (int u = 0; u < 8; u++) w[u] = W[u * 256 + t];
    for (int k0 = 0; k0 < K; k0 += 8) {
        float wn[8];
        bool more = (k0 + 8) < K;
#pragma unroll
        for (int u = 0; u < 8; u++) wn[u] = more ? W[(k0 + 8 + u) * 256 + t] : 0.f;
#pragma unroll
        for (int u = 0; u < 8; u++) {
            const float4* xp = (const float4*)&xs[(k0 + u) * 8];
            float4 xa = xp[0], xb = xp[1];
            acc[0] += xa.x * w[u]; acc[1] += xa.y * w[u];
            acc[2] += xa.z * w[u]; acc[3] += xa.w * w[u];
            acc[4] += xb.x * w[u]; acc[5] += xb.y * w[u];
            acc[6] += xb.z * w[u]; acc[7] += xb.w * w[u];
        }
#pragma unroll
        for (int u = 0; u < 8; u++) w[u] = wn[u];
    }
}

// N=400 (two column slots: m1=t, m2=t+256 if t<144), ld = 400
__device__ __forceinline__ void gemm8n400(const float* __restrict__ W,
                                          const float* __restrict__ xs,
                                          float accA[8], float accB[8],
                                          int K, int t, bool s2)
{
    float w1[8], w2[8];
#pragma unroll
    for (int u = 0; u < 8; u++) {
        w1[u] = W[u * 400 + t];
        w2[u] = s2 ? W[u * 400 + t + 256] : 0.f;
    }
    for (int k0 = 0; k0 < K; k0 += 8) {
        float n1[8], n2[8];
        bool more = (k0 + 8) < K;
#pragma unroll
        for (int u = 0; u < 8; u++) {
            n1[u] = more ? W[(k0 + 8 + u) * 400 + t] : 0.f;
            n2[u] = (more && s2) ? W[(k0 + 8 + u) * 400 + t + 256] : 0.f;
        }
#pragma unroll
        for (int u = 0; u < 8; u++) {
            const float4* xp = (const float4*)&xs[(k0 + u) * 8];
            float4 xa = xp[0], xb = xp[1];
            accA[0] += xa.x * w1[u]; accA[1] += xa.y * w1[u];
            accA[2] += xa.z * w1[u]; accA[3] += xa.w * w1[u];
            accA[4] += xb.x * w1[u]; accA[5] += xb.y * w1[u];
            accA[6] += xb.z * w1[u]; accA[7] += xb.w * w1[u];
            accB[0] += xa.x * w2[u]; accB[1] += xa.y * w2[u];
            accB[2] += xa.z * w2[u]; accB[3] += xa.w * w2[u];
            accB[4] += xb.x * w2[u]; accB[5] += xb.y * w2[u];
            accB[6] += xb.z * w2[u]; accB[7] += xb.w * w2[u];
        }
#pragma unroll
        for (int u = 0; u < 8; u++) { w1[u] = n1[u]; w2[u] = n2[u]; }
    }
}

__device__ __forceinline__ void store_x(float* xs, int t, const float acc[8])
{
    *(float4*)&xs[t * 8]     = make_float4(acc[0], acc[1], acc[2], acc[3]);
    *(float4*)&xs[t * 8 + 4] = make_float4(acc[4], acc[5], acc[6], acc[7]);
}

__device__ __forceinline__ void bsum8(const float v[8], float* wred, float* stats, int t)
{
    int lane = t & 31, warp = t >> 5;
#pragma unroll
    for (int r = 0; r < 8; r++) {
        float x = v[r];
#pragma unroll
        for (int o = 16; o; o >>= 1) x += __shfl_xor_sync(0xffffffffu, x, o);
        if (lane == 0) wred[warp * 8 + r] = x;
    }
    __syncthreads();
    if (t < 8) {
        float s = 0.f;
#pragma unroll
        for (int w = 0; w < 8; w++) s += wred[w * 8 + t];
        stats[t] = s;
    }
    __syncthreads();
}

__device__ __forceinline__ void bmax8(const float v[8], float* wred, float* stats, int t)
{
    int lane = t & 31, warp = t >> 5;
#pragma unroll
    for (int r = 0; r < 8; r++) {
        float x = v[r];
#pragma unroll
        for (int o = 16; o; o >>= 1) x = fmaxf(x, __shfl_xor_sync(0xffffffffu, x, o));
        if (lane == 0) wred[warp * 8 + r] = x;
    }
    __syncthreads();
    if (t < 8) {
        float s = -1e30f;
#pragma unroll
        for (int w = 0; w < 8; w++) s = fmaxf(s, wred[w * 8 + t]);
        stats[t] = s;
    }
    __syncthreads();
}

// LayerNorm in-place on acc[8] (per-row stats over all 256 threads)
__device__ __forceinline__ void ln_apply(float acc[8],
                                         const float* __restrict__ g,
                                         const float* __restrict__ b,
                                         int t, float* wred, float* stats)
{
    int lane = t & 31, warp = t >> 5;
#pragma unroll
    for (int r = 0; r < 8; r++) {
        float s = acc[r], q = acc[r] * acc[r];
#pragma unroll
        for (int o = 16; o; o >>= 1) {
            s += __shfl_xor_sync(0xffffffffu, s, o);
            q += __shfl_xor_sync(0xffffffffu, q, o);
        }
        if (lane == 0) { wred[warp * 16 + r] = s; wred[warp * 16 + 8 + r] = q; }
    }
    __syncthreads();
    if (t < 8) {
        float s = 0.f, q = 0.f;
#pragma unroll
        for (int w = 0; w < 8; w++) { s += wred[w * 16 + t]; q += wred[w * 16 + 8 + t]; }
        float mean = s * (1.f / 256.f);
        float var  = q * (1.f / 256.f) - mean * mean;
        stats[t]     = mean;
        stats[8 + t] = rsqrtf(var + 1e-5f);
    }
    __syncthreads();
    float gg = g[t], bb = b[t];
#pragma unroll
    for (int r = 0; r < 8; r++)
        acc[r] = (acc[r] - stats[r]) * stats[8 + r] * gg + bb;
}

// smem: xsA 2048 | xsB 2048 | ctx 2048 | sc 12800 | wred 128 | stats 64
#define SM_FLOATS (2048 * 3 + 12800 + 128 + 64)

__global__ __launch_bounds__(256)
void mega_kernel(const float* __restrict__ mf, const float* __restrict__ regtab,
                 const int* __restrict__ rid,
                 const float* __restrict__ ew1, const float* __restrict__ eb1,
                 const float* __restrict__ l1g, const float* __restrict__ l1b,
                 const float* __restrict__ ew2, const float* __restrict__ eb2,
                 const float* __restrict__ l2g, const float* __restrict__ l2b,
                 const float* __restrict__ ew3, const float* __restrict__ eb3,
                 const float* __restrict__ gw1, const float* __restrict__ gb1,
                 const float* __restrict__ gw2, const float* __restrict__ gb2,
                 const float* __restrict__ gw3, const float* __restrict__ gb3,
                 const float* __restrict__ wq,  const float* __restrict__ bq,
                 const float* __restrict__ wo,  const float* __restrict__ bo,
                 const float* __restrict__ meT, const float* __restrict__ kT,
                 const float* __restrict__ v,   const float* __restrict__ mp,
                 float* __restrict__ out_pred, float* __restrict__ out_w,
                 float* __restrict__ divp)
{
    extern __shared__ float sm[];
    float* xsA   = sm;
    float* xsB   = xsA + 2048;
    float* ctxs  = xsB + 2048;
    float* sc    = ctxs + 2048;
    float* wred  = sc + 12800;
    float* stats = wred + 128;

    const int t  = threadIdx.x;
    const int b0 = blockIdx.x * 8;
    const bool s2 = (t < 144);

    // ---- stage input: concat(mf, regime_emb) in k-major [k][8] ----
    if (t < 160) {
#pragma unroll
        for (int r = 0; r < 8; r++) {
            float x = (t < 128) ? mf[(b0 + r) * 128 + t]
                                : regtab[rid[b0 + r] * 32 + (t - 128)];
            xsA[t * 8 + r] = x;
        }
    }
    __syncthreads();

    float acc[8];

    // ---- enc1: K=160, LN, GELU ----
    { float b = eb1[t];
#pragma unroll
      for (int r = 0; r < 8; r++) acc[r] = b; }
    gemm8(ew1, xsA, acc, 160, t);
    ln_apply(acc, l1g, l1b, t, wred, stats);
#pragma unroll
    for (int r = 0; r < 8; r++) acc[r] = gelu_exact(acc[r]);
    store_x(xsB, t, acc);
    __syncthreads();

    // ---- enc2 ----
    { float b = eb2[t];
#pragma unroll
      for (int r = 0; r < 8; r++) acc[r] = b; }
    gemm8(ew2, xsB, acc, 256, t);
    ln_apply(acc, l2g, l2b, t, wred, stats);
#pragma unroll
    for (int r = 0; r < 8; r++) acc[r] = gelu_exact(acc[r]);
    store_x(xsA, t, acc);
    __syncthreads();

    // ---- enc3 -> ctx ----
    { float b = eb3[t];
#pragma unroll
      for (int r = 0; r < 8; r++) acc[r] = b; }
    gemm8(ew3, xsA, acc, 256, t);
    store_x(ctxs, t, acc);
    __syncthreads();

    // ---- wg1 ----
    { float b = gb1[t];
#pragma unroll
      for (int r = 0; r < 8; r++) acc[r] = b; }
    gemm8(gw1, ctxs, acc, 256, t);
#pragma unroll
    for (int r = 0; r < 8; r++) acc[r] = gelu_exact(acc[r]);
    store_x(xsB, t, acc);
    __syncthreads();

    // ---- wg2 ----
    { float b = gb2[t];
#pragma unroll
      for (int r = 0; r < 8; r++) acc[r] = b; }
    gemm8(gw2, xsB, acc, 256, t);
#pragma unroll
    for (int r = 0; r < 8; r++) acc[r] = gelu_exact(acc[r]);
    store_x(xsA, t, acc);
    __syncthreads();

    // ---- wg3 -> base (kept in registers) ----
    float baseA[8], baseB[8];
#pragma unroll
    for (int r = 0; r < 8; r++) { baseA[r] = 0.f; baseB[r] = 0.f; }
    gemm8n400(gw3, xsA, baseA, baseB, 256, t, s2);
    { float b1v = gb3[t], b2v = s2 ? gb3[t + 256] : 0.f;
#pragma unroll
      for (int r = 0; r < 8; r++) { baseA[r] += b1v; baseB[r] += b2v; } }

    // ---- q = ctx@wq + bq ----
    { float b = bq[t];
#pragma unroll
      for (int r = 0; r < 8; r++) acc[r] = b; }
    gemm8(wq, ctxs, acc, 256, t);
    store_x(xsB, t, acc);
    __syncthreads();

    // ---- scores per head + write to sc[h][m][r] ----
    for (int h = 0; h < 4; h++) {
        float sA[8], sB[8];
#pragma unroll
        for (int r = 0; r < 8; r++) { sA[r] = 0.f; sB[r] = 0.f; }
        gemm8n400(kT + h * 64 * 400, xsB + h * 64 * 8, sA, sB, 64, t, s2);
        float* dst = sc + (h * 400 + t) * 8;
        *(float4*)&dst[0] = make_float4(sA[0]*0.125f, sA[1]*0.125f, sA[2]*0.125f, sA[3]*0.125f);
        *(float4*)&dst[4] = make_float4(sA[4]*0.125f, sA[5]*0.125f, sA[6]*0.125f, sA[7]*0.125f);
        if (s2) {
            float* d2 = sc + (h * 400 + t + 256) * 8;
            *(float4*)&d2[0] = make_float4(sB[0]*0.125f, sB[1]*0.125f, sB[2]*0.125f, sB[3]*0.125f);
            *(float4*)&d2[4] = make_float4(sB[4]*0.125f, sB[5]*0.125f, sB[6]*0.125f, sB[7]*0.125f);
        }
    }
    __syncthreads();

    // ---- softmax over m for each (h, r): 32 pairs, warp each ----
    {
        int warp = t >> 5, lane = t & 31;
        for (int p = warp; p < 32; p += 8) {
            int h = p >> 3, r = p & 7;
            float* base = sc + (h * 400) * 8 + r;
            float mx = -1e30f;
            for (int m = lane; m < 400; m += 32) mx = fmaxf(mx, base[m * 8]);
#pragma unroll
            for (int o = 16; o; o >>= 1) mx = fmaxf(mx, __shfl_xor_sync(0xffffffffu, mx, o));
            float s = 0.f;
            for (int m = lane; m < 400; m += 32) {
                float e = expf(base[m * 8] - mx);
                base[m * 8] = e;
                s += e;
            }
#pragma unroll
            for (int o = 16; o; o >>= 1) s += __shfl_xor_sync(0xffffffffu, s, o);
            float inv = 1.f / s;
            for (int m = lane; m < 400; m += 32) base[m * 8] *= inv;
        }
    }
    __syncthreads();

    // ---- att[r][t] = sum_m a[h(t)][r][m] * v[m][t] ----
#pragma unroll
    for (int r = 0; r < 8; r++) acc[r] = 0.f;
    gemm8(v, sc + (t >> 6) * 400 * 8, acc, 400, t);
    store_x(xsA, t, acc);
    __syncthreads();

    // ---- attended = att@wo + bo ----
    { float b = bo[t];
#pragma unroll
      for (int r = 0; r < 8; r++) acc[r] = b; }
    gemm8(wo, xsA, acc, 256, t);
    store_x(xsB, t, acc);
    __syncthreads();

    // ---- attention_weights = attended @ me^T ----
    float awA[8], awB[8];
#pragma unroll
    for (int r = 0; r < 8; r++) { awA[r] = 0.f; awB[r] = 0.f; }
    gemm8n400(meT, xsB, awA, awB, 256, t, s2);

    // ---- combine: softmax -> clip -> renorm -> w, prediction, diversity ----
    float lA[8], lB[8], m8[8];
#pragma unroll
    for (int r = 0; r < 8; r++) {
        lA[r] = baseA[r] + 0.5f * awA[r];
        lB[r] = s2 ? (baseB[r] + 0.5f * awB[r]) : -1e30f;
        m8[r] = fmaxf(lA[r], lB[r]);
    }
    bmax8(m8, wred, stats, t);
    float eA[8], eB[8];
#pragma unroll
    for (int r = 0; r < 8; r++) {
        float mx = stats[r];
        eA[r] = expf(lA[r] - mx);
        eB[r] = s2 ? expf(lB[r] - mx) : 0.f;
        m8[r] = eA[r] + eB[r];
    }
    bsum8(m8, wred, stats, t);
    float wA[8], wB[8];
#pragma unroll
    for (int r = 0; r < 8; r++) {
        float inv = 1.f / stats[r];
        wA[r] = fmaxf(eA[r] * inv, 0.001f);
        wB[r] = s2 ? fmaxf(eB[r] * inv, 0.001f) : 0.f;
        m8[r] = wA[r] + wB[r];
    }
    bsum8(m8, wred, stats, t);

    float p0[8], p1[8], p2[8], sx[8], sy[8], sz[8], tt[8];
#pragma unroll
    for (int r = 0; r < 8; r++) {
        float inv2 = 1.f / stats[r];
        wA[r] *= inv2;
        out_w[(size_t)(b0 + r) * 400 + t] = wA[r];
        const float* q1 = mp + ((size_t)(b0 + r) * 400 + t) * 3;
        float x0 = q1[0], x1 = q1[1], x2 = q1[2];
        float n2 = x0 * x0 + x1 * x1 + x2 * x2;
        float invn = 1.f / fmaxf(sqrtf(n2), 1e-12f);
        p0[r] = wA[r] * x0; p1[r] = wA[r] * x1; p2[r] = wA[r] * x2;
        sx[r] = x0 * invn;  sy[r] = x1 * invn;  sz[r] = x2 * invn;
        tt[r] = n2 * invn * invn;
        if (s2) {
            wB[r] *= inv2;
            out_w[(size_t)(b0 + r) * 400 + t + 256] = wB[r];
            const float* q2 = mp + ((size_t)(b0 + r) * 400 + t + 256) * 3;
            float y0 = q2[0], y1 = q2[1], y2 = q2[2];
            float nn = y0 * y0 + y1 * y1 + y2 * y2;
            float iv = 1.f / fmaxf(sqrtf(nn), 1e-12f);
            p0[r] += wB[r] * y0; p1[r] += wB[r] * y1; p2[r] += wB[r] * y2;
            sx[r] += y0 * iv;    sy[r] += y1 * iv;    sz[r] += y2 * iv;
            tt[r] += nn * iv * iv;
        }
    }
    bsum8(p0, wred, stats, t); float P0 = stats[t & 7];
    bsum8(p1, wred, stats, t); float P1 = stats[t & 7];
    bsum8(p2, wred, stats, t); float P2 = stats[t & 7];
    bsum8(sx, wred, stats, t); float SX = stats[t & 7];
    bsum8(sy, wred, stats, t); float SY = stats[t & 7];
    bsum8(sz, wred, stats, t); float SZ = stats[t & 7];
    bsum8(tt, wred, stats, t); float TT = stats[t & 7];
    if (t < 8) {
        out_pred[(b0 + t) * 3 + 0] = P0;
        out_pred[(b0 + t) * 3 + 1] = P1;
        out_pred[(b0 + t) * 3 + 2] = P2;
        divp[b0 + t] = SX * SX + SY * SY + SZ * SZ - TT;
    }
}

__global__ __launch_bounds__(256)
void final_div(const float* __restrict__ divp, float* __restrict__ outp)
{
    __shared__ float sm[256];
    int tid = threadIdx.x;
    float s = 0.f;
    for (int i = tid; i < 1024; i += 256) s += divp[i];
    sm[tid] = s; __syncthreads();
    for (int st = 128; st > 0; st >>= 1) {
        if (tid < st) sm[tid] += sm[tid + st];
        __syncthreads();
    }
    if (tid == 0)
        outp[0] = sm[0] / (1024.0f * 400.0f * 399.0f) * 0.1f;
}

// =================================================================
extern "C" void kernel_launch(void* const* d_in, const int* in_sizes, int n_in,
                              void* d_out, int out_size)
{
    const float* mf     = (const float*)d_in[0];
    const float* mp     = (const float*)d_in[1];
    const float* regtab = (const float*)d_in[2];
    const float* enc_w1 = (const float*)d_in[3];
    const float* enc_b1 = (const float*)d_in[4];
    const float* ln1g   = (const float*)d_in[5];
    const float* ln1b   = (const float*)d_in[6];
    const float* enc_w2 = (const float*)d_in[7];
    const float* enc_b2 = (const float*)d_in[8];
    const float* ln2g   = (const float*)d_in[9];
    const float* ln2b   = (const float*)d_in[10];
    const float* enc_w3 = (const float*)d_in[11];
    const float* enc_b3 = (const float*)d_in[12];
    const float* wg_w1  = (const float*)d_in[13];
    const float* wg_b1  = (const float*)d_in[14];
    const float* wg_w2  = (const float*)d_in[15];
    const float* wg_b2  = (const float*)d_in[16];
    const float* wg_w3  = (const float*)d_in[17];
    const float* wg_b3  = (const float*)d_in[18];
    const float* memb   = (const float*)d_in[19];
    const float* proj_w = (const float*)d_in[20];
    const float* proj_b = (const float*)d_in[21];
    const float* wq     = (const float*)d_in[22];
    const float* bq     = (const float*)d_in[23];
    const float* wk     = (const float*)d_in[24];
    const float* bk     = (const float*)d_in[25];
    const float* wv     = (const float*)d_in[26];
    const float* bv     = (const float*)d_in[27];
    const float* wo     = (const float*)d_in[28];
    const float* bo     = (const float*)d_in[29];
    const int*   rid    = (const int*)d_in[30];
    float* out = (float*)d_out;

    float *meT, *kT, *v, *divp;
    cudaGetSymbolAddress((void**)&meT,  g_meT);
    cudaGetSymbolAddress((void**)&kT,   g_kT);
    cudaGetSymbolAddress((void**)&v,    g_v);
    cudaGetSymbolAddress((void**)&divp, g_div);

    const int smem_bytes = SM_FLOATS * (int)sizeof(float);
    cudaFuncSetAttribute(mega_kernel, cudaFuncAttributeMaxDynamicSharedMemorySize,
                         smem_bytes);

    prep_kernel<<<100, 256>>>(memb, proj_w, proj_b, wk, bk, wv, bv, meT, kT, v);

    mega_kernel<<<128, 256, smem_bytes>>>(
        mf, regtab, rid,
        enc_w1, enc_b1, ln1g, ln1b,
        enc_w2, enc_b2, ln2g, ln2b,
        enc_w3, enc_b3,
        wg_w1, wg_b1, wg_w2, wg_b2, wg_w3, wg_b3,
        wq, bq, wo, bo,
        meT, kT, v, mp,
        out, out + 3072, divp);

    final_div<<<1, 256>>>(divp, out + 412672);
}

// round 3
// speedup vs baseline: 1.4805x; 1.0840x over previous
#include <cuda_runtime.h>
#include <math.h>

typedef unsigned long long ull;

// ---------------- scratch (no allocation allowed) ----------------
__device__ float g_me [400 * 256];   // me row-major [m][k]
__device__ float g_meT[256 * 400];   // me transposed [k][m]
__device__ float g_kT [256 * 400];   // k transposed  [dfull][m]
__device__ float g_v  [400 * 256];   // v normal      [m][dfull]
__device__ float g_div[1024];

__device__ __forceinline__ float gelu_exact(float x) {
    return 0.5f * x * (1.0f + erff(x * 0.70710678118654752440f));
}

// ---------------- f32x2 packed helpers ----------------
__device__ __forceinline__ ull pack2(float w) {
    ull r;
    asm("mov.b64 %0, {%1, %1};" : "=l"(r) : "r"(__float_as_uint(w)));
    return r;
}
__device__ __forceinline__ void vfma(ull& d, ull a, ull b) {
    asm("fma.rn.f32x2 %0, %1, %2, %0;" : "+l"(d) : "l"(a), "l"(b));
}
__device__ __forceinline__ float lo2(ull v) { return __uint_as_float((unsigned)v); }
__device__ __forceinline__ float hi2(ull v) { return __uint_as_float((unsigned)(v >> 32)); }

// =================================================================
// column GEMM core: thread t owns output column t (ld 256).
// NP row-pairs (2*NP rows), x in smem k-major [k][2*NP].
// distance-2 weight prefetch (two 8-k chunks in flight).
// =================================================================
template<int K, int NP>
__device__ __forceinline__ void gemm_col(const float* __restrict__ W,
                                         const float* __restrict__ xs,
                                         ull acc[NP], int t)
{
    float w0[8], w1[8];
#pragma unroll
    for (int u = 0; u < 8; u++) w0[u] = W[u * 256 + t];
#pragma unroll
    for (int u = 0; u < 8; u++) w1[u] = (K > 8) ? W[(8 + u) * 256 + t] : 0.f;
    for (int k0 = 0; k0 < K; k0 += 8) {
        float wn[8];
#pragma unroll
        for (int u = 0; u < 8; u++)
            wn[u] = (k0 + 16 < K) ? W[(k0 + 16 + u) * 256 + t] : 0.f;
#pragma unroll
        for (int u = 0; u < 8; u++) {
            ull wp = pack2(w0[u]);
            const ull* xp = (const ull*)&xs[(k0 + u) * (2 * NP)];
#pragma unroll
            for (int q = 0; q < NP / 2; q++) {
                ulonglong2 xv = *(const ulonglong2*)(xp + 2 * q);
                vfma(acc[2 * q],     xv.x, wp);
                vfma(acc[2 * q + 1], xv.y, wp);
            }
            if (NP & 1) vfma(acc[NP - 1], xp[NP - 1], wp);
        }
#pragma unroll
        for (int u = 0; u < 8; u++) { w0[u] = w1[u]; w1[u] = wn[u]; }
    }
}

// N=400 variant (ld 400): col slots t and t+256 (t<144), 8 rows.
template<int K>
__device__ __forceinline__ void gemm_col400(const float* __restrict__ W,
                                            const float* __restrict__ xs,
                                            ull accA[4], ull accB[4],
                                            int t, bool s2)
{
    float a0[8], a1[8], b0[8], b1[8];
#pragma unroll
    for (int u = 0; u < 8; u++) {
        a0[u] = W[u * 400 + t];
        b0[u] = s2 ? W[u * 400 + t + 256] : 0.f;
    }
#pragma unroll
    for (int u = 0; u < 8; u++) {
        a1[u] = (K > 8) ? W[(8 + u) * 400 + t] : 0.f;
        b1[u] = (K > 8 && s2) ? W[(8 + u) * 400 + t + 256] : 0.f;
    }
    for (int k0 = 0; k0 < K; k0 += 8) {
        float an[8], bn[8];
#pragma unroll
        for (int u = 0; u < 8; u++) {
            an[u] = (k0 + 16 < K) ? W[(k0 + 16 + u) * 400 + t] : 0.f;
            bn[u] = (k0 + 16 < K && s2) ? W[(k0 + 16 + u) * 400 + t + 256] : 0.f;
        }
#pragma unroll
        for (int u = 0; u < 8; u++) {
            ull wa = pack2(a0[u]);
            ull wb = pack2(b0[u]);
            const ull* xp = (const ull*)&xs[(k0 + u) * 8];
            ulonglong2 x0 = *(const ulonglong2*)(xp);
            ulonglong2 x1 = *(const ulonglong2*)(xp + 2);
            vfma(accA[0], x0.x, wa); vfma(accA[1], x0.y, wa);
            vfma(accA[2], x1.x, wa); vfma(accA[3], x1.y, wa);
            vfma(accB[0], x0.x, wb); vfma(accB[1], x0.y, wb);
            vfma(accB[2], x1.x, wb); vfma(accB[3], x1.y, wb);
        }
#pragma unroll
        for (int u = 0; u < 8; u++) { a0[u] = a1[u]; a1[u] = an[u];
                                      b0[u] = b1[u]; b1[u] = bn[u]; }
    }
}

__device__ __forceinline__ void set_bias4(ull a[4], float b) {
    ull bp = pack2(b);
    a[0] = bp; a[1] = bp; a[2] = bp; a[3] = bp;
}
__device__ __forceinline__ void unpack8(const ull a[4], float x[8]) {
#pragma unroll
    for (int q = 0; q < 4; q++) { x[2 * q] = lo2(a[q]); x[2 * q + 1] = hi2(a[q]); }
}

// =================================================================
// prep_me: me = memb@proj_w + b      (100 blocks x 4 member rows)
// writes me row-major AND meT transposed
// =================================================================
__global__ __launch_bounds__(256)
void prep_me(const float* __restrict__ memb,
             const float* __restrict__ proj_w, const float* __restrict__ proj_b,
             float* __restrict__ me, float* __restrict__ meT)
{
    __shared__ float xm[64 * 4];
    const int t = threadIdx.x;
    const int g0 = blockIdx.x * 4;
    { int r = t >> 6, k = t & 63; xm[k * 4 + r] = memb[(g0 + r) * 64 + k]; }
    __syncthreads();

    ull acc[2];
    { ull bp = pack2(proj_b[t]); acc[0] = bp; acc[1] = bp; }
    gemm_col<64, 2>(proj_w, xm, acc, t);

    float m0 = lo2(acc[0]), m1 = hi2(acc[0]), m2 = lo2(acc[1]), m3 = hi2(acc[1]);
    me[(g0 + 0) * 256 + t] = m0;
    me[(g0 + 1) * 256 + t] = m1;
    me[(g0 + 2) * 256 + t] = m2;
    me[(g0 + 3) * 256 + t] = m3;
    *(float4*)&meT[t * 400 + g0] = make_float4(m0, m1, m2, m3);
}

// =================================================================
// prep_kv: k = me@wk+bk (stored transposed), v = me@wv+bv
// grid (100, 2): y=0 -> kT, y=1 -> v.  4 member rows per block.
// =================================================================
__global__ __launch_bounds__(256)
void prep_kv(const float* __restrict__ me,
             const float* __restrict__ wk, const float* __restrict__ bk,
             const float* __restrict__ wv, const float* __restrict__ bv,
             float* __restrict__ kT, float* __restrict__ v)
{
    __shared__ float xm[256 * 4];
    const int t = threadIdx.x;
    const int g0 = blockIdx.x * 4;
    const bool isV = (blockIdx.y != 0);

    float r0 = me[(g0 + 0) * 256 + t];
    float r1 = me[(g0 + 1) * 256 + t];
    float r2 = me[(g0 + 2) * 256 + t];
    float r3 = me[(g0 + 3) * 256 + t];
    *(float4*)&xm[t * 4] = make_float4(r0, r1, r2, r3);
    __syncthreads();

    const float* W = isV ? wv : wk;
    const float* B = isV ? bv : bk;
    ull acc[2];
    { ull bp = pack2(B[t]); acc[0] = bp; acc[1] = bp; }
    gemm_col<256, 2>(W, xm, acc, t);

    float o0 = lo2(acc[0]), o1 = hi2(acc[0]), o2 = lo2(acc[1]), o3 = hi2(acc[1]);
    if (!isV) {
        *(float4*)&kT[t * 400 + g0] = make_float4(o0, o1, o2, o3);
    } else {
        v[(g0 + 0) * 256 + t] = o0;
        v[(g0 + 1) * 256 + t] = o1;
        v[(g0 + 2) * 256 + t] = o2;
        v[(g0 + 3) * 256 + t] = o3;
    }
}

// =================================================================
// mega kernel helpers (8 rows per block, 256 threads)
// =================================================================
__device__ __forceinline__ void store_x(float* xs, int t, const float acc[8])
{
    *(float4*)&xs[t * 8]     = make_float4(acc[0], acc[1], acc[2], acc[3]);
    *(float4*)&xs[t * 8 + 4] = make_float4(acc[4], acc[5], acc[6], acc[7]);
}

__device__ __forceinline__ void bsum8(const float v[8], float* wred, float* stats, int t)
{
    int lane = t & 31, warp = t >> 5;
#pragma unroll
    for (int r = 0; r < 8; r++) {
        float x = v[r];
#pragma unroll
        for (int o = 16; o; o >>= 1) x += __shfl_xor_sync(0xffffffffu, x, o);
        if (lane == 0) wred[warp * 8 + r] = x;
    }
    __syncthreads();
    if (t < 8) {
        float s = 0.f;
#pragma unroll
        for (int w = 0; w < 8; w++) s += wred[w * 8 + t];
        stats[t] = s;
    }
    __syncthreads();
}

__device__ __forceinline__ void bmax8(const float v[8], float* wred, float* stats, int t)
{
    int lane = t & 31, warp = t >> 5;
#pragma unroll
    for (int r = 0; r < 8; r++) {
        float x = v[r];
#pragma unroll
        for (int o = 16; o; o >>= 1) x = fmaxf(x, __shfl_xor_sync(0xffffffffu, x, o));
        if (lane == 0) wred[warp * 8 + r] = x;
    }
    __syncthreads();
    if (t < 8) {
        float s = -1e30f;
#pragma unroll
        for (int w = 0; w < 8; w++) s = fmaxf(s, wred[w * 8 + t]);
        stats[t] = s;
    }
    __syncthreads();
}

__device__ __forceinline__ void ln_apply(float acc[8],
                                         const float* __restrict__ g,
                                         const float* __restrict__ b,
                                         int t, float* wred, float* stats)
{
    int lane = t & 31, warp = t >> 5;
#pragma unroll
    for (int r = 0; r < 8; r++) {
        float s = acc[r], q = acc[r] * acc[r];
#pragma unroll
        for (int o = 16; o; o >>= 1) {
            s += __shfl_xor_sync(0xffffffffu, s, o);
            q += __shfl_xor_sync(0xffffffffu, q, o);
        }
        if (lane == 0) { wred[warp * 16 + r] = s; wred[warp * 16 + 8 + r] = q; }
    }
    __syncthreads();
    if (t < 8) {
        float s = 0.f, q = 0.f;
#pragma unroll
        for (int w = 0; w < 8; w++) { s += wred[w * 16 + t]; q += wred[w * 16 + 8 + t]; }
        float mean = s * (1.f / 256.f);
        float var  = q * (1.f / 256.f) - mean * mean;
        stats[t]     = mean;
        stats[8 + t] = rsqrtf(var + 1e-5f);
    }
    __syncthreads();
    float gg = g[t], bb = b[t];
#pragma unroll
    for (int r = 0; r < 8; r++)
        acc[r] = (acc[r] - stats[r]) * stats[8 + r] * gg + bb;
}

// smem: xsA 2048 | xsB 2048 | ctx 2048 | sc 12800 | wred 128 | stats 64
#define SM_FLOATS (2048 * 3 + 12800 + 128 + 64)

__global__ __launch_bounds__(256)
void mega_kernel(const float* __restrict__ mf, const float* __restrict__ regtab,
                 const int* __restrict__ rid,
                 const float* __restrict__ ew1, const float* __restrict__ eb1,
                 const float* __restrict__ l1g, const float* __restrict__ l1b,
                 const float* __restrict__ ew2, const float* __restrict__ eb2,
                 const float* __restrict__ l2g, const float* __restrict__ l2b,
                 const float* __restrict__ ew3, const float* __restrict__ eb3,
                 const float* __restrict__ gw1, const float* __restrict__ gb1,
                 const float* __restrict__ gw2, const float* __restrict__ gb2,
                 const float* __restrict__ gw3, const float* __restrict__ gb3,
                 const float* __restrict__ wq,  const float* __restrict__ bq,
                 const float* __restrict__ wo,  const float* __restrict__ bo,
                 const float* __restrict__ meT, const float* __restrict__ kT,
                 const float* __restrict__ v,   const float* __restrict__ mp,
                 float* __restrict__ out_pred, float* __restrict__ out_w,
                 float* __restrict__ divp)
{
    extern __shared__ float sm[];
    float* xsA   = sm;
    float* xsB   = xsA + 2048;
    float* ctxs  = xsB + 2048;
    float* sc    = ctxs + 2048;
    float* wred  = sc + 12800;
    float* stats = wred + 128;

    const int t  = threadIdx.x;
    const int b0 = blockIdx.x * 8;
    const bool s2 = (t < 144);

    if (t < 160) {
#pragma unroll
        for (int r = 0; r < 8; r++) {
            float x = (t < 128) ? mf[(b0 + r) * 128 + t]
                                : regtab[rid[b0 + r] * 32 + (t - 128)];
            xsA[t * 8 + r] = x;
        }
    }
    __syncthreads();

    float acc[8]; ull a2[4];

    // ---- enc1: K=160, LN, GELU ----
    set_bias4(a2, eb1[t]);
    gemm_col<160, 4>(ew1, xsA, a2, t);
    unpack8(a2, acc);
    ln_apply(acc, l1g, l1b, t, wred, stats);
#pragma unroll
    for (int r = 0; r < 8; r++) acc[r] = gelu_exact(acc[r]);
    store_x(xsB, t, acc);
    __syncthreads();

    // ---- enc2 ----
    set_bias4(a2, eb2[t]);
    gemm_col<256, 4>(ew2, xsB, a2, t);
    unpack8(a2, acc);
    ln_apply(acc, l2g, l2b, t, wred, stats);
#pragma unroll
    for (int r = 0; r < 8; r++) acc[r] = gelu_exact(acc[r]);
    store_x(xsA, t, acc);
    __syncthreads();

    // ---- enc3 -> ctx ----
    set_bias4(a2, eb3[t]);
    gemm_col<256, 4>(ew3, xsA, a2, t);
    unpack8(a2, acc);
    store_x(ctxs, t, acc);
    __syncthreads();

    // ---- wg1 ----
    set_bias4(a2, gb1[t]);
    gemm_col<256, 4>(gw1, ctxs, a2, t);
    unpack8(a2, acc);
#pragma unroll
    for (int r = 0; r < 8; r++) acc[r] = gelu_exact(acc[r]);
    store_x(xsB, t, acc);
    __syncthreads();

    // ---- wg2 ----
    set_bias4(a2, gb2[t]);
    gemm_col<256, 4>(gw2, xsB, a2, t);
    unpack8(a2, acc);
#pragma unroll
    for (int r = 0; r < 8; r++) acc[r] = gelu_exact(acc[r]);
    store_x(xsA, t, acc);
    __syncthreads();

    // ---- wg3 -> base (kept in registers) ----
    float baseA[8], baseB[8];
    {
        ull aA[4] = {0, 0, 0, 0}, aB[4] = {0, 0, 0, 0};
        gemm_col400<256>(gw3, xsA, aA, aB, t, s2);
        unpack8(aA, baseA); unpack8(aB, baseB);
        float b1v = gb3[t], b2v = s2 ? gb3[t + 256] : 0.f;
#pragma unroll
        for (int r = 0; r < 8; r++) { baseA[r] += b1v; baseB[r] += b2v; }
    }

    // ---- q = ctx@wq + bq ----
    set_bias4(a2, bq[t]);
    gemm_col<256, 4>(wq, ctxs, a2, t);
    unpack8(a2, acc);
    store_x(xsB, t, acc);
    __syncthreads();

    // ---- scores per head -> sc[h][m][r] ----
    for (int h = 0; h < 4; h++) {
        ull aA[4] = {0, 0, 0, 0}, aB[4] = {0, 0, 0, 0};
        gemm_col400<64>(kT + h * 64 * 400, xsB + h * 64 * 8, aA, aB, t, s2);
        float sA[8], sB[8];
        unpack8(aA, sA); unpack8(aB, sB);
        float* dst = sc + (h * 400 + t) * 8;
        *(float4*)&dst[0] = make_float4(sA[0]*0.125f, sA[1]*0.125f, sA[2]*0.125f, sA[3]*0.125f);
        *(float4*)&dst[4] = make_float4(sA[4]*0.125f, sA[5]*0.125f, sA[6]*0.125f, sA[7]*0.125f);
        if (s2) {
            float* d2 = sc + (h * 400 + t + 256) * 8;
            *(float4*)&d2[0] = make_float4(sB[0]*0.125f, sB[1]*0.125f, sB[2]*0.125f, sB[3]*0.125f);
            *(float4*)&d2[4] = make_float4(sB[4]*0.125f, sB[5]*0.125f, sB[6]*0.125f, sB[7]*0.125f);
        }
    }
    __syncthreads();

    // ---- softmax over m for each (h, r): 32 pairs, warp each ----
    {
        int warp = t >> 5, lane = t & 31;
        for (int p = warp; p < 32; p += 8) {
            int h = p >> 3, r = p & 7;
            float* base = sc + (h * 400) * 8 + r;
            float mx = -1e30f;
            for (int m = lane; m < 400; m += 32) mx = fmaxf(mx, base[m * 8]);
#pragma unroll
            for (int o = 16; o; o >>= 1) mx = fmaxf(mx, __shfl_xor_sync(0xffffffffu, mx, o));
            float s = 0.f;
            for (int m = lane; m < 400; m += 32) {
                float e = expf(base[m * 8] - mx);
                base[m * 8] = e;
                s += e;
            }
#pragma unroll
            for (int o = 16; o; o >>= 1) s += __shfl_xor_sync(0xffffffffu, s, o);
            float inv = 1.f / s;
            for (int m = lane; m < 400; m += 32) base[m * 8] *= inv;
        }
    }
    __syncthreads();

    // ---- att[r][t] = sum_m a[h(t)][r][m] * v[m][t] ----
    { ull z[4] = {0, 0, 0, 0};
      gemm_col<400, 4>(v, sc + (t >> 6) * 400 * 8, z, t);
      unpack8(z, acc); }
    store_x(xsA, t, acc);
    __syncthreads();

    // ---- attended = att@wo + bo ----
    set_bias4(a2, bo[t]);
    gemm_col<256, 4>(wo, xsA, a2, t);
    unpack8(a2, acc);
    store_x(xsB, t, acc);
    __syncthreads();

    // ---- attention_weights = attended @ me^T ----
    float awA[8], awB[8];
    {
        ull aA[4] = {0, 0, 0, 0}, aB[4] = {0, 0, 0, 0};
        gemm_col400<256>(meT, xsB, aA, aB, t, s2);
        unpack8(aA, awA); unpack8(aB, awB);
    }

    // ---- combine: softmax -> clip -> renorm -> w, prediction, diversity ----
    float lA[8], lB[8], m8[8];
#pragma unroll
    for (int r = 0; r < 8; r++) {
        lA[r] = baseA[r] + 0.5f * awA[r];
        lB[r] = s2 ? (baseB[r] + 0.5f * awB[r]) : -1e30f;
        m8[r] = fmaxf(lA[r], lB[r]);
    }
    bmax8(m8, wred, stats, t);
    float eA[8], eB[8];
#pragma unroll
    for (int r = 0; r < 8; r++) {
        float mx = stats[r];
        eA[r] = expf(lA[r] - mx);
        eB[r] = s2 ? expf(lB[r] - mx) : 0.f;
        m8[r] = eA[r] + eB[r];
    }
    bsum8(m8, wred, stats, t);
    float wA[8], wB[8];
#pragma unroll
    for (int r = 0; r < 8; r++) {
        float inv = 1.f / stats[r];
        wA[r] = fmaxf(eA[r] * inv, 0.001f);
        wB[r] = s2 ? fmaxf(eB[r] * inv, 0.001f) : 0.f;
        m8[r] = wA[r] + wB[r];
    }
    bsum8(m8, wred, stats, t);

    float p0[8], p1[8], p2[8], sx[8], sy[8], sz[8], tt[8];
#pragma unroll
    for (int r = 0; r < 8; r++) {
        float inv2 = 1.f / stats[r];
        wA[r] *= inv2;
        out_w[(size_t)(b0 + r) * 400 + t] = wA[r];
        const float* q1 = mp + ((size_t)(b0 + r) * 400 + t) * 3;
        float x0 = q1[0], x1 = q1[1], x2 = q1[2];
        float n2 = x0 * x0 + x1 * x1 + x2 * x2;
        float invn = 1.f / fmaxf(sqrtf(n2), 1e-12f);
        p0[r] = wA[r] * x0; p1[r] = wA[r] * x1; p2[r] = wA[r] * x2;
        sx[r] = x0 * invn;  sy[r] = x1 * invn;  sz[r] = x2 * invn;
        tt[r] = n2 * invn * invn;
        if (s2) {
            wB[r] *= inv2;
            out_w[(size_t)(b0 + r) * 400 + t + 256] = wB[r];
            const float* q2 = mp + ((size_t)(b0 + r) * 400 + t + 256) * 3;
            float y0 = q2[0], y1 = q2[1], y2 = q2[2];
            float nn = y0 * y0 + y1 * y1 + y2 * y2;
            float iv = 1.f / fmaxf(sqrtf(nn), 1e-12f);
            p0[r] += wB[r] * y0; p1[r] += wB[r] * y1; p2[r] += wB[r] * y2;
            sx[r] += y0 * iv;    sy[r] += y1 * iv;    sz[r] += y2 * iv;
            tt[r] += nn * iv * iv;
        }
    }
    bsum8(p0, wred, stats, t); float P0 = stats[t & 7];
    bsum8(p1, wred, stats, t); float P1 = stats[t & 7];
    bsum8(p2, wred, stats, t); float P2 = stats[t & 7];
    bsum8(sx, wred, stats, t); float SX = stats[t & 7];
    bsum8(sy, wred, stats, t); float SY = stats[t & 7];
    bsum8(sz, wred, stats, t); float SZ = stats[t & 7];
    bsum8(tt, wred, stats, t); float TT = stats[t & 7];
    if (t < 8) {
        out_pred[(b0 + t) * 3 + 0] = P0;
        out_pred[(b0 + t) * 3 + 1] = P1;
        out_pred[(b0 + t) * 3 + 2] = P2;
        divp[b0 + t] = SX * SX + SY * SY + SZ * SZ - TT;
    }
}

__global__ __launch_bounds__(256)
void final_div(const float* __restrict__ divp, float* __restrict__ outp)
{
    __shared__ float sm[256];
    int tid = threadIdx.x;
    float s = 0.f;
    for (int i = tid; i < 1024; i += 256) s += divp[i];
    sm[tid] = s; __syncthreads();
    for (int st = 128; st > 0; st >>= 1) {
        if (tid < st) sm[tid] += sm[tid + st];
        __syncthreads();
    }
    if (tid == 0)
        outp[0] = sm[0] / (1024.0f * 400.0f * 399.0f) * 0.1f;
}

// =================================================================
extern "C" void kernel_launch(void* const* d_in, const int* in_sizes, int n_in,
                              void* d_out, int out_size)
{
    const float* mf     = (const float*)d_in[0];
    const float* mp     = (const float*)d_in[1];
    const float* regtab = (const float*)d_in[2];
    const float* enc_w1 = (const float*)d_in[3];
    const float* enc_b1 = (const float*)d_in[4];
    const float* ln1g   = (const float*)d_in[5];
    const float* ln1b   = (const float*)d_in[6];
    const float* enc_w2 = (const float*)d_in[7];
    const float* enc_b2 = (const float*)d_in[8];
    const float* ln2g   = (const float*)d_in[9];
    const float* ln2b   = (const float*)d_in[10];
    const float* enc_w3 = (const float*)d_in[11];
    const float* enc_b3 = (const float*)d_in[12];
    const float* wg_w1  = (const float*)d_in[13];
    const float* wg_b1  = (const float*)d_in[14];
    const float* wg_w2  = (const float*)d_in[15];
    const float* wg_b2  = (const float*)d_in[16];
    const float* wg_w3  = (const float*)d_in[17];
    const float* wg_b3  = (const float*)d_in[18];
    const float* memb   = (const float*)d_in[19];
    const float* proj_w = (const float*)d_in[20];
    const float* proj_b = (const float*)d_in[21];
    const float* wq     = (const float*)d_in[22];
    const float* bq     = (const float*)d_in[23];
    const float* wk     = (const float*)d_in[24];
    const float* bk     = (const float*)d_in[25];
    const float* wv     = (const float*)d_in[26];
    const float* bv     = (const float*)d_in[27];
    const float* wo     = (const float*)d_in[28];
    const float* bo     = (const float*)d_in[29];
    const int*   rid    = (const int*)d_in[30];
    float* out = (float*)d_out;

    float *me, *meT, *kT, *v, *divp;
    cudaGetSymbolAddress((void**)&me,   g_me);
    cudaGetSymbolAddress((void**)&meT,  g_meT);
    cudaGetSymbolAddress((void**)&kT,   g_kT);
    cudaGetSymbolAddress((void**)&v,    g_v);
    cudaGetSymbolAddress((void**)&divp, g_div);

    const int smem_bytes = SM_FLOATS * (int)sizeof(float);
    cudaFuncSetAttribute(mega_kernel, cudaFuncAttributeMaxDynamicSharedMemorySize,
                         smem_bytes);

    prep_me<<<100, 256>>>(memb, proj_w, proj_b, me, meT);
    prep_kv<<<dim3(100, 2), 256>>>(me, wk, bk, wv, bv, kT, v);

    mega_kernel<<<128, 256, smem_bytes>>>(
        mf, regtab, rid,
        enc_w1, enc_b1, ln1g, ln1b,
        enc_w2, enc_b2, ln2g, ln2b,
        enc_w3, enc_b3,
        wg_w1, wg_b1, wg_w2, wg_b2, wg_w3, wg_b3,
        wq, bq, wo, bo,
        meT, kT, v, mp,
        out, out + 3072, divp);

    final_div<<<1, 256>>>(divp, out + 412672);
}

// round 4
// speedup vs baseline: 1.6639x; 1.1239x over previous
#include <cuda_runtime.h>
#include <math.h>

typedef unsigned long long ull;

// ---------------- scratch (no allocation allowed) ----------------
__device__ float g_meT[256 * 400];   // me transposed [k][m]
__device__ float g_kT [256 * 400];   // k transposed  [dfull][m]
__device__ float g_v  [400 * 256];   // v normal      [m][dfull]
__device__ float g_div[1024];
__device__ int   g_cnt;

__device__ __forceinline__ float gelu_exact(float x) {
    return 0.5f * x * (1.0f + erff(x * 0.70710678118654752440f));
}

// ---------------- f32x2 packed helpers ----------------
__device__ __forceinline__ ull pack2(float w) {
    ull r;
    asm("mov.b64 %0, {%1, %1};" : "=l"(r) : "r"(__float_as_uint(w)));
    return r;
}
__device__ __forceinline__ void vfma(ull& d, ull a, ull b) {
    asm("fma.rn.f32x2 %0, %1, %2, %0;" : "+l"(d) : "l"(a), "l"(b));
}
__device__ __forceinline__ float lo2(ull v) { return __uint_as_float((unsigned)v); }
__device__ __forceinline__ float hi2(ull v) { return __uint_as_float((unsigned)(v >> 32)); }

// =================================================================
// column GEMM core: thread t owns output column t (ld 256).
// NP row-pairs (2*NP rows), x in smem k-major [k][2*NP].
// distance-2 weight prefetch (two 8-k chunks in flight).
// =================================================================
template<int K, int NP>
__device__ __forceinline__ void gemm_col(const float* __restrict__ W,
                                         const float* __restrict__ xs,
                                         ull acc[NP], int t)
{
    float w0[8], w1[8];
#pragma unroll
    for (int u = 0; u < 8; u++) w0[u] = W[u * 256 + t];
#pragma unroll
    for (int u = 0; u < 8; u++) w1[u] = (K > 8) ? W[(8 + u) * 256 + t] : 0.f;
    for (int k0 = 0; k0 < K; k0 += 8) {
        float wn[8];
#pragma unroll
        for (int u = 0; u < 8; u++)
            wn[u] = (k0 + 16 < K) ? W[(k0 + 16 + u) * 256 + t] : 0.f;
#pragma unroll
        for (int u = 0; u < 8; u++) {
            ull wp = pack2(w0[u]);
            const ull* xp = (const ull*)&xs[(k0 + u) * (2 * NP)];
            if (NP == 1) {
                vfma(acc[0], xp[0], wp);
            } else {
                ulonglong2 xv = *(const ulonglong2*)xp;
                vfma(acc[0], xv.x, wp);
                vfma(acc[1], xv.y, wp);
            }
        }
#pragma unroll
        for (int u = 0; u < 8; u++) { w0[u] = w1[u]; w1[u] = wn[u]; }
    }
}

// N=400 variant (ld 400): col slots t and t+256 (t<144), 4 rows.
template<int K>
__device__ __forceinline__ void gemm_col400(const float* __restrict__ W,
                                            const float* __restrict__ xs,
                                            ull accA[2], ull accB[2],
                                            int t, bool s2)
{
    float a0[8], a1[8], b0[8], b1[8];
#pragma unroll
    for (int u = 0; u < 8; u++) {
        a0[u] = W[u * 400 + t];
        b0[u] = s2 ? W[u * 400 + t + 256] : 0.f;
    }
#pragma unroll
    for (int u = 0; u < 8; u++) {
        a1[u] = (K > 8) ? W[(8 + u) * 400 + t] : 0.f;
        b1[u] = (K > 8 && s2) ? W[(8 + u) * 400 + t + 256] : 0.f;
    }
    for (int k0 = 0; k0 < K; k0 += 8) {
        float an[8], bn[8];
#pragma unroll
        for (int u = 0; u < 8; u++) {
            an[u] = (k0 + 16 < K) ? W[(k0 + 16 + u) * 400 + t] : 0.f;
            bn[u] = (k0 + 16 < K && s2) ? W[(k0 + 16 + u) * 400 + t + 256] : 0.f;
        }
#pragma unroll
        for (int u = 0; u < 8; u++) {
            ull wa = pack2(a0[u]);
            ull wb = pack2(b0[u]);
            ulonglong2 xv = *(const ulonglong2*)&xs[(k0 + u) * 4];
            vfma(accA[0], xv.x, wa); vfma(accA[1], xv.y, wa);
            vfma(accB[0], xv.x, wb); vfma(accB[1], xv.y, wb);
        }
#pragma unroll
        for (int u = 0; u < 8; u++) { a0[u] = a1[u]; a1[u] = an[u];
                                      b0[u] = b1[u]; b1[u] = bn[u]; }
    }
}

__device__ __forceinline__ void set_bias2(ull a[2], float b) {
    ull bp = pack2(b);
    a[0] = bp; a[1] = bp;
}
__device__ __forceinline__ void unpack4(const ull a[2], float x[4]) {
    x[0] = lo2(a[0]); x[1] = hi2(a[0]); x[2] = lo2(a[1]); x[3] = hi2(a[1]);
}

// =================================================================
// prep: me = memb@proj_w+b (recomputed per y-branch; row-local chain)
//       y=0: write meT, compute kT    y=1: compute v
// grid (100, 2), 4 member rows per block.
// =================================================================
__global__ __launch_bounds__(256)
void prep_kernel(const float* __restrict__ memb,
                 const float* __restrict__ proj_w, const float* __restrict__ proj_b,
                 const float* __restrict__ wk, const float* __restrict__ bk,
                 const float* __restrict__ wv, const float* __restrict__ bv,
                 float* __restrict__ meT, float* __restrict__ kT, float* __restrict__ v)
{
    __shared__ float xm[64 * 4];
    __shared__ float mes[256 * 4];
    const int t = threadIdx.x;
    const int g0 = blockIdx.x * 4;
    const bool isV = (blockIdx.y != 0);

    { int r = t >> 6, k = t & 63; xm[k * 4 + r] = memb[(g0 + r) * 64 + k]; }
    __syncthreads();

    ull acc[2];
    set_bias2(acc, proj_b[t]);
    gemm_col<64, 2>(proj_w, xm, acc, t);
    float m[4]; unpack4(acc, m);
    *(float4*)&mes[t * 4] = make_float4(m[0], m[1], m[2], m[3]);
    if (!isV)
        *(float4*)&meT[t * 400 + g0] = make_float4(m[0], m[1], m[2], m[3]);
    __syncthreads();

    const float* W = isV ? wv : wk;
    const float* B = isV ? bv : bk;
    set_bias2(acc, B[t]);
    gemm_col<256, 2>(W, mes, acc, t);
    float o[4]; unpack4(acc, o);
    if (!isV) {
        *(float4*)&kT[t * 400 + g0] = make_float4(o[0], o[1], o[2], o[3]);
    } else {
        v[(g0 + 0) * 256 + t] = o[0];
        v[(g0 + 1) * 256 + t] = o[1];
        v[(g0 + 2) * 256 + t] = o[2];
        v[(g0 + 3) * 256 + t] = o[3];
    }
}

// =================================================================
// mega kernel helpers (4 rows per block, 256 threads, 256 blocks)
// =================================================================
__device__ __forceinline__ void store_x(float* xs, int t, const float acc[4])
{
    *(float4*)&xs[t * 4] = make_float4(acc[0], acc[1], acc[2], acc[3]);
}

__device__ __forceinline__ void bsum4(const float v[4], float* wred, float* stats, int t)
{
    int lane = t & 31, warp = t >> 5;
#pragma unroll
    for (int r = 0; r < 4; r++) {
        float x = v[r];
#pragma unroll
        for (int o = 16; o; o >>= 1) x += __shfl_xor_sync(0xffffffffu, x, o);
        if (lane == 0) wred[warp * 4 + r] = x;
    }
    __syncthreads();
    if (t < 4) {
        float s = 0.f;
#pragma unroll
        for (int w = 0; w < 8; w++) s += wred[w * 4 + t];
        stats[t] = s;
    }
    __syncthreads();
}

__device__ __forceinline__ void bmax4(const float v[4], float* wred, float* stats, int t)
{
    int lane = t & 31, warp = t >> 5;
#pragma unroll
    for (int r = 0; r < 4; r++) {
        float x = v[r];
#pragma unroll
        for (int o = 16; o; o >>= 1) x = fmaxf(x, __shfl_xor_sync(0xffffffffu, x, o));
        if (lane == 0) wred[warp * 4 + r] = x;
    }
    __syncthreads();
    if (t < 4) {
        float s = -1e30f;
#pragma unroll
        for (int w = 0; w < 8; w++) s = fmaxf(s, wred[w * 4 + t]);
        stats[t] = s;
    }
    __syncthreads();
}

__device__ __forceinline__ void ln_apply(float acc[4],
                                         const float* __restrict__ g,
                                         const float* __restrict__ b,
                                         int t, float* wred, float* stats)
{
    int lane = t & 31, warp = t >> 5;
#pragma unroll
    for (int r = 0; r < 4; r++) {
        float s = acc[r], q = acc[r] * acc[r];
#pragma unroll
        for (int o = 16; o; o >>= 1) {
            s += __shfl_xor_sync(0xffffffffu, s, o);
            q += __shfl_xor_sync(0xffffffffu, q, o);
        }
        if (lane == 0) { wred[warp * 8 + r] = s; wred[warp * 8 + 4 + r] = q; }
    }
    __syncthreads();
    if (t < 4) {
        float s = 0.f, q = 0.f;
#pragma unroll
        for (int w = 0; w < 8; w++) { s += wred[w * 8 + t]; q += wred[w * 8 + 4 + t]; }
        float mean = s * (1.f / 256.f);
        float var  = q * (1.f / 256.f) - mean * mean;
        stats[t]     = mean;
        stats[4 + t] = rsqrtf(var + 1e-5f);
    }
    __syncthreads();
    float gg = g[t], bb = b[t];
#pragma unroll
    for (int r = 0; r < 4; r++)
        acc[r] = (acc[r] - stats[r]) * stats[4 + r] * gg + bb;
}

// smem: xsA 1024 | xsB 1024 | ctx 1024 | sc 6400 | wred 64 | stats 32
#define SM_FLOATS (1024 * 3 + 6400 + 64 + 32)

__global__ __launch_bounds__(256, 2)
void mega_kernel(const float* __restrict__ mf, const float* __restrict__ regtab,
                 const int* __restrict__ rid,
                 const float* __restrict__ ew1, const float* __restrict__ eb1,
                 const float* __restrict__ l1g, const float* __restrict__ l1b,
                 const float* __restrict__ ew2, const float* __restrict__ eb2,
                 const float* __restrict__ l2g, const float* __restrict__ l2b,
                 const float* __restrict__ ew3, const float* __restrict__ eb3,
                 const float* __restrict__ gw1, const float* __restrict__ gb1,
                 const float* __restrict__ gw2, const float* __restrict__ gb2,
                 const float* __restrict__ gw3, const float* __restrict__ gb3,
                 const float* __restrict__ wq,  const float* __restrict__ bq,
                 const float* __restrict__ wo,  const float* __restrict__ bo,
                 const float* __restrict__ meT, const float* __restrict__ kT,
                 const float* __restrict__ v,   const float* __restrict__ mp,
                 float* __restrict__ out_pred, float* __restrict__ out_w,
                 float* __restrict__ divp, float* __restrict__ out_div)
{
    extern __shared__ float sm[];
    float* xsA   = sm;
    float* xsB   = xsA + 1024;
    float* ctxs  = xsB + 1024;
    float* sc    = ctxs + 1024;
    float* wred  = sc + 6400;
    float* stats = wred + 64;
    __shared__ int lastFlag;

    const int t  = threadIdx.x;
    const int b0 = blockIdx.x * 4;
    const bool s2 = (t < 144);

    if (t < 160) {
#pragma unroll
        for (int r = 0; r < 4; r++) {
            float x = (t < 128) ? mf[(b0 + r) * 128 + t]
                                : regtab[rid[b0 + r] * 32 + (t - 128)];
            xsA[t * 4 + r] = x;
        }
    }
    __syncthreads();

    float acc[4]; ull a2[2];

    // ---- enc1: K=160, LN, GELU ----
    set_bias2(a2, eb1[t]);
    gemm_col<160, 2>(ew1, xsA, a2, t);
    unpack4(a2, acc);
    ln_apply(acc, l1g, l1b, t, wred, stats);
#pragma unroll
    for (int r = 0; r < 4; r++) acc[r] = gelu_exact(acc[r]);
    store_x(xsB, t, acc);
    __syncthreads();

    // ---- enc2 ----
    set_bias2(a2, eb2[t]);
    gemm_col<256, 2>(ew2, xsB, a2, t);
    unpack4(a2, acc);
    ln_apply(acc, l2g, l2b, t, wred, stats);
#pragma unroll
    for (int r = 0; r < 4; r++) acc[r] = gelu_exact(acc[r]);
    store_x(xsA, t, acc);
    __syncthreads();

    // ---- enc3 -> ctx ----
    set_bias2(a2, eb3[t]);
    gemm_col<256, 2>(ew3, xsA, a2, t);
    unpack4(a2, acc);
    store_x(ctxs, t, acc);
    __syncthreads();

    // ---- wg1 ----
    set_bias2(a2, gb1[t]);
    gemm_col<256, 2>(gw1, ctxs, a2, t);
    unpack4(a2, acc);
#pragma unroll
    for (int r = 0; r < 4; r++) acc[r] = gelu_exact(acc[r]);
    store_x(xsB, t, acc);
    __syncthreads();

    // ---- wg2 ----
    set_bias2(a2, gb2[t]);
    gemm_col<256, 2>(gw2, xsB, a2, t);
    unpack4(a2, acc);
#pragma unroll
    for (int r = 0; r < 4; r++) acc[r] = gelu_exact(acc[r]);
    store_x(xsA, t, acc);
    __syncthreads();

    // ---- wg3 -> base (kept in registers) ----
    float baseA[4], baseB[4];
    {
        ull aA[2] = {0, 0}, aB[2] = {0, 0};
        gemm_col400<256>(gw3, xsA, aA, aB, t, s2);
        unpack4(aA, baseA); unpack4(aB, baseB);
        float b1v = gb3[t], b2v = s2 ? gb3[t + 256] : 0.f;
#pragma unroll
        for (int r = 0; r < 4; r++) { baseA[r] += b1v; baseB[r] += b2v; }
    }

    // ---- q = ctx@wq + bq ----
    set_bias2(a2, bq[t]);
    gemm_col<256, 2>(wq, ctxs, a2, t);
    unpack4(a2, acc);
    store_x(xsB, t, acc);
    __syncthreads();

    // ---- scores per head -> sc[h][m][r] ----
    for (int h = 0; h < 4; h++) {
        ull aA[2] = {0, 0}, aB[2] = {0, 0};
        gemm_col400<64>(kT + h * 64 * 400, xsB + h * 64 * 4, aA, aB, t, s2);
        float sA[4], sB[4];
        unpack4(aA, sA); unpack4(aB, sB);
        *(float4*)&sc[(h * 400 + t) * 4] =
            make_float4(sA[0]*0.125f, sA[1]*0.125f, sA[2]*0.125f, sA[3]*0.125f);
        if (s2)
            *(float4*)&sc[(h * 400 + t + 256) * 4] =
                make_float4(sB[0]*0.125f, sB[1]*0.125f, sB[2]*0.125f, sB[3]*0.125f);
    }
    __syncthreads();

    // ---- softmax over m for each (h, r): 16 pairs, warp each ----
    {
        int warp = t >> 5, lane = t & 31;
        for (int p = warp; p < 16; p += 8) {
            int h = p >> 2, r = p & 3;
            float* base = sc + h * 400 * 4 + r;
            float mx = -1e30f;
            for (int m = lane; m < 400; m += 32) mx = fmaxf(mx, base[m * 4]);
#pragma unroll
            for (int o = 16; o; o >>= 1) mx = fmaxf(mx, __shfl_xor_sync(0xffffffffu, mx, o));
            float s = 0.f;
            for (int m = lane; m < 400; m += 32) {
                float e = expf(base[m * 4] - mx);
                base[m * 4] = e;
                s += e;
            }
#pragma unroll
            for (int o = 16; o; o >>= 1) s += __shfl_xor_sync(0xffffffffu, s, o);
            float inv = 1.f / s;
            for (int m = lane; m < 400; m += 32) base[m * 4] *= inv;
        }
    }
    __syncthreads();

    // ---- att[r][t] = sum_m a[h(t)][r][m] * v[m][t] ----
    { ull z[2] = {0, 0};
      gemm_col<400, 2>(v, sc + (t >> 6) * 400 * 4, z, t);
      unpack4(z, acc); }
    store_x(xsA, t, acc);
    __syncthreads();

    // ---- attended = att@wo + bo ----
    set_bias2(a2, bo[t]);
    gemm_col<256, 2>(wo, xsA, a2, t);
    unpack4(a2, acc);
    store_x(xsB, t, acc);
    __syncthreads();

    // ---- attention_weights = attended @ me^T ----
    float awA[4], awB[4];
    {
        ull aA[2] = {0, 0}, aB[2] = {0, 0};
        gemm_col400<256>(meT, xsB, aA, aB, t, s2);
        unpack4(aA, awA); unpack4(aB, awB);
    }

    // ---- combine: softmax -> clip -> renorm -> w, prediction, diversity ----
    float lA[4], lB[4], m4[4];
#pragma unroll
    for (int r = 0; r < 4; r++) {
        lA[r] = baseA[r] + 0.5f * awA[r];
        lB[r] = s2 ? (baseB[r] + 0.5f * awB[r]) : -1e30f;
        m4[r] = fmaxf(lA[r], lB[r]);
    }
    bmax4(m4, wred, stats, t);
    float eA[4], eB[4];
#pragma unroll
    for (int r = 0; r < 4; r++) {
        float mx = stats[r];
        eA[r] = expf(lA[r] - mx);
        eB[r] = s2 ? expf(lB[r] - mx) : 0.f;
        m4[r] = eA[r] + eB[r];
    }
    bsum4(m4, wred, stats, t);
    float wA[4], wB[4];
#pragma unroll
    for (int r = 0; r < 4; r++) {
        float inv = 1.f / stats[r];
        wA[r] = fmaxf(eA[r] * inv, 0.001f);
        wB[r] = s2 ? fmaxf(eB[r] * inv, 0.001f) : 0.f;
        m4[r] = wA[r] + wB[r];
    }
    bsum4(m4, wred, stats, t);

    float p0[4], p1[4], p2[4], sx[4], sy[4], sz[4], tt[4];
#pragma unroll
    for (int r = 0; r < 4; r++) {
        float inv2 = 1.f / stats[r];
        wA[r] *= inv2;
        out_w[(size_t)(b0 + r) * 400 + t] = wA[r];
        const float* q1 = mp + ((size_t)(b0 + r) * 400 + t) * 3;
        float x0 = q1[0], x1 = q1[1], x2 = q1[2];
        float n2 = x0 * x0 + x1 * x1 + x2 * x2;
        float invn = 1.f / fmaxf(sqrtf(n2), 1e-12f);
        p0[r] = wA[r] * x0; p1[r] = wA[r] * x1; p2[r] = wA[r] * x2;
        sx[r] = x0 * invn;  sy[r] = x1 * invn;  sz[r] = x2 * invn;
        tt[r] = n2 * invn * invn;
        if (s2) {
            wB[r] *= inv2;
            out_w[(size_t)(b0 + r) * 400 + t + 256] = wB[r];
            const float* q2 = mp + ((size_t)(b0 + r) * 400 + t + 256) * 3;
            float y0 = q2[0], y1 = q2[1], y2 = q2[2];
            float nn = y0 * y0 + y1 * y1 + y2 * y2;
            float iv = 1.f / fmaxf(sqrtf(nn), 1e-12f);
            p0[r] += wB[r] * y0; p1[r] += wB[r] * y1; p2[r] += wB[r] * y2;
            sx[r] += y0 * iv;    sy[r] += y1 * iv;    sz[r] += y2 * iv;
            tt[r] += nn * iv * iv;
        }
    }
    bsum4(p0, wred, stats, t); float P0 = stats[t & 3];
    bsum4(p1, wred, stats, t); float P1 = stats[t & 3];
    bsum4(p2, wred, stats, t); float P2 = stats[t & 3];
    bsum4(sx, wred, stats, t); float SX = stats[t & 3];
    bsum4(sy, wred, stats, t); float SY = stats[t & 3];
    bsum4(sz, wred, stats, t); float SZ = stats[t & 3];
    bsum4(tt, wred, stats, t); float TT = stats[t & 3];
    if (t < 4) {
        out_pred[(b0 + t) * 3 + 0] = P0;
        out_pred[(b0 + t) * 3 + 1] = P1;
        out_pred[(b0 + t) * 3 + 2] = P2;
        divp[b0 + t] = SX * SX + SY * SY + SZ * SZ - TT;
    }

    // ---- last-block deterministic final reduction ----
    __syncthreads();
    if (t == 0) {
        __threadfence();
        int c = atomicAdd(&g_cnt, 1);
        lastFlag = (c == (int)gridDim.x - 1);
    }
    __syncthreads();
    if (lastFlag) {
        float s = 0.f;
        for (int i = t; i < 1024; i += 256) s += divp[i];
        int lane = t & 31, warp = t >> 5;
#pragma unroll
        for (int o = 16; o; o >>= 1) s += __shfl_xor_sync(0xffffffffu, s, o);
        if (lane == 0) wred[warp] = s;
        __syncthreads();
        if (t == 0) {
            float tot = 0.f;
#pragma unroll
            for (int w = 0; w < 8; w++) tot += wred[w];
            out_div[0] = tot / (1024.0f * 400.0f * 399.0f) * 0.1f;
            g_cnt = 0;
        }
    }
}

// =================================================================
extern "C" void kernel_launch(void* const* d_in, const int* in_sizes, int n_in,
                              void* d_out, int out_size)
{
    const float* mf     = (const float*)d_in[0];
    const float* mp     = (const float*)d_in[1];
    const float* regtab = (const float*)d_in[2];
    const float* enc_w1 = (const float*)d_in[3];
    const float* enc_b1 = (const float*)d_in[4];
    const float* ln1g   = (const float*)d_in[5];
    const float* ln1b   = (const float*)d_in[6];
    const float* enc_w2 = (const float*)d_in[7];
    const float* enc_b2 = (const float*)d_in[8];
    const float* ln2g   = (const float*)d_in[9];
    const float* ln2b   = (const float*)d_in[10];
    const float* enc_w3 = (const float*)d_in[11];
    const float* enc_b3 = (const float*)d_in[12];
    const float* wg_w1  = (const float*)d_in[13];
    const float* wg_b1  = (const float*)d_in[14];
    const float* wg_w2  = (const float*)d_in[15];
    const float* wg_b2  = (const float*)d_in[16];
    const float* wg_w3  = (const float*)d_in[17];
    const float* wg_b3  = (const float*)d_in[18];
    const float* memb   = (const float*)d_in[19];
    const float* proj_w = (const float*)d_in[20];
    const float* proj_b = (const float*)d_in[21];
    const float* wq     = (const float*)d_in[22];
    const float* bq     = (const float*)d_in[23];
    const float* wk     = (const float*)d_in[24];
    const float* bk     = (const float*)d_in[25];
    const float* wv     = (const float*)d_in[26];
    const float* bv     = (const float*)d_in[27];
    const float* wo     = (const float*)d_in[28];
    const float* bo     = (const float*)d_in[29];
    const int*   rid    = (const int*)d_in[30];
    float* out = (float*)d_out;

    float *meT, *kT, *v, *divp;
    cudaGetSymbolAddress((void**)&meT,  g_meT);
    cudaGetSymbolAddress((void**)&kT,   g_kT);
    cudaGetSymbolAddress((void**)&v,    g_v);
    cudaGetSymbolAddress((void**)&divp, g_div);

    const int smem_bytes = SM_FLOATS * (int)sizeof(float);
    cudaFuncSetAttribute(mega_kernel, cudaFuncAttributeMaxDynamicSharedMemorySize,
                         smem_bytes);

    prep_kernel<<<dim3(100, 2), 256>>>(memb, proj_w, proj_b, wk, bk, wv, bv,
                                       meT, kT, v);

    mega_kernel<<<256, 256, smem_bytes>>>(
        mf, regtab, rid,
        enc_w1, enc_b1, ln1g, ln1b,
        enc_w2, enc_b2, ln2g, ln2b,
        enc_w3, enc_b3,
        wg_w1, wg_b1, wg_w2, wg_b2, wg_w3, wg_b3,
        wq, bq, wo, bo,
        meT, kT, v, mp,
        out, out + 3072, divp, out + 412672);
}

// round 5
// speedup vs baseline: 1.9003x; 1.1421x over previous
#include <cuda_runtime.h>
#include <math.h>

typedef unsigned long long ull;

// ---------------- scratch (no allocation allowed) ----------------
__device__ float g_meT[256 * 400];   // me transposed [k][m]
__device__ float g_kT [256 * 400];   // k transposed  [dfull][m]
__device__ float g_v  [400 * 256];   // v normal      [m][dfull]
__device__ float g_div[1024];
__device__ int   g_cnt;

__device__ __forceinline__ float gelu_exact(float x) {
    return 0.5f * x * (1.0f + erff(x * 0.70710678118654752440f));
}

// ---------------- f32x2 packed helpers ----------------
__device__ __forceinline__ ull pack2(float w) {
    ull r;
    asm("mov.b64 %0, {%1, %1};" : "=l"(r) : "r"(__float_as_uint(w)));
    return r;
}
__device__ __forceinline__ void vfma(ull& d, ull a, ull b) {
    asm("fma.rn.f32x2 %0, %1, %2, %0;" : "+l"(d) : "l"(a), "l"(b));
}
__device__ __forceinline__ float lo2(ull v) { return __uint_as_float((unsigned)v); }
__device__ __forceinline__ float hi2(ull v) { return __uint_as_float((unsigned)(v >> 32)); }

// =================================================================
// column GEMM core: thread t owns output column t (ld 256).
// 4 rows (2 ull accumulators), x in smem k-major [k][4].
// Fully-unrolled chunk loop, 3-buffer rotation -> no MOVs, true
// distance-2 prefetch, immediate-offset loads.
// =================================================================
template<int K>
__device__ __forceinline__ void gemm_col(const float* __restrict__ W,
                                         const float* __restrict__ xs,
                                         ull acc[2], int t)
{
    constexpr int NCH = K / 8;
    const float* Wt = W + t;
    float w[3][8];
#pragma unroll
    for (int u = 0; u < 8; u++) w[0][u] = Wt[u * 256];
    if (NCH > 1) {
#pragma unroll
        for (int u = 0; u < 8; u++) w[1][u] = Wt[(8 + u) * 256];
    }
#pragma unroll
    for (int n = 0; n < NCH; n++) {
        if (n + 2 < NCH) {
#pragma unroll
            for (int u = 0; u < 8; u++)
                w[(n + 2) % 3][u] = Wt[((n + 2) * 8 + u) * 256];
        }
#pragma unroll
        for (int u = 0; u < 8; u++) {
            ull wp = pack2(w[n % 3][u]);
            ulonglong2 xv = *(const ulonglong2*)&xs[(n * 8 + u) * 4];
            vfma(acc[0], xv.x, wp);
            vfma(acc[1], xv.y, wp);
        }
    }
}

// N=400 variant (ld 400): col slots t and t+256 (t<144), 4 rows.
template<int K>
__device__ __forceinline__ void gemm_col400(const float* __restrict__ W,
                                            const float* __restrict__ xs,
                                            ull accA[2], ull accB[2],
                                            int t, bool s2)
{
    constexpr int NCH = K / 8;
    const float* Wa = W + t;
    const float* Wb = W + t + 256;
    float a[3][8], b[3][8];
#pragma unroll
    for (int u = 0; u < 8; u++) {
        a[0][u] = Wa[u * 400];
        b[0][u] = s2 ? Wb[u * 400] : 0.f;
    }
    if (NCH > 1) {
#pragma unroll
        for (int u = 0; u < 8; u++) {
            a[1][u] = Wa[(8 + u) * 400];
            b[1][u] = s2 ? Wb[(8 + u) * 400] : 0.f;
        }
    }
#pragma unroll
    for (int n = 0; n < NCH; n++) {
        if (n + 2 < NCH) {
#pragma unroll
            for (int u = 0; u < 8; u++) {
                a[(n + 2) % 3][u] = Wa[((n + 2) * 8 + u) * 400];
                b[(n + 2) % 3][u] = s2 ? Wb[((n + 2) * 8 + u) * 400] : 0.f;
            }
        }
#pragma unroll
        for (int u = 0; u < 8; u++) {
            ull wa = pack2(a[n % 3][u]);
            ull wb = pack2(b[n % 3][u]);
            ulonglong2 xv = *(const ulonglong2*)&xs[(n * 8 + u) * 4];
            vfma(accA[0], xv.x, wa); vfma(accA[1], xv.y, wa);
            vfma(accB[0], xv.x, wb); vfma(accB[1], xv.y, wb);
        }
    }
}

__device__ __forceinline__ void set_bias2(ull a[2], float b) {
    ull bp = pack2(b);
    a[0] = bp; a[1] = bp;
}
__device__ __forceinline__ void unpack4(const ull a[2], float x[4]) {
    x[0] = lo2(a[0]); x[1] = hi2(a[0]); x[2] = lo2(a[1]); x[3] = hi2(a[1]);
}

// =================================================================
// prep: me = memb@proj_w+b (recomputed per y-branch; row-local chain)
//       y=0: write meT, compute kT    y=1: compute v
// grid (100, 2), 4 member rows per block.
// =================================================================
__global__ __launch_bounds__(256)
void prep_kernel(const float* __restrict__ memb,
                 const float* __restrict__ proj_w, const float* __restrict__ proj_b,
                 const float* __restrict__ wk, const float* __restrict__ bk,
                 const float* __restrict__ wv, const float* __restrict__ bv,
                 float* __restrict__ meT, float* __restrict__ kT, float* __restrict__ v)
{
    __shared__ float xm[64 * 4];
    __shared__ float mes[256 * 4];
    const int t = threadIdx.x;
    const int g0 = blockIdx.x * 4;
    const bool isV = (blockIdx.y != 0);

    { int r = t >> 6, k = t & 63; xm[k * 4 + r] = memb[(g0 + r) * 64 + k]; }
    __syncthreads();

    ull acc[2];
    set_bias2(acc, proj_b[t]);
    gemm_col<64>(proj_w, xm, acc, t);
    float m[4]; unpack4(acc, m);
    *(float4*)&mes[t * 4] = make_float4(m[0], m[1], m[2], m[3]);
    if (!isV)
        *(float4*)&meT[t * 400 + g0] = make_float4(m[0], m[1], m[2], m[3]);
    __syncthreads();

    const float* W = isV ? wv : wk;
    const float* B = isV ? bv : bk;
    set_bias2(acc, B[t]);
    gemm_col<256>(W, mes, acc, t);
    float o[4]; unpack4(acc, o);
    if (!isV) {
        *(float4*)&kT[t * 400 + g0] = make_float4(o[0], o[1], o[2], o[3]);
    } else {
        v[(g0 + 0) * 256 + t] = o[0];
        v[(g0 + 1) * 256 + t] = o[1];
        v[(g0 + 2) * 256 + t] = o[2];
        v[(g0 + 3) * 256 + t] = o[3];
    }
}

// =================================================================
// mega kernel helpers (4 rows per block, 256 threads, 256 blocks)
// =================================================================
__device__ __forceinline__ void store_x(float* xs, int t, const float acc[4])
{
    *(float4*)&xs[t * 4] = make_float4(acc[0], acc[1], acc[2], acc[3]);
}

__device__ __forceinline__ void bsum4(const float v[4], float* wred, float* stats, int t)
{
    int lane = t & 31, warp = t >> 5;
#pragma unroll
    for (int r = 0; r < 4; r++) {
        float x = v[r];
#pragma unroll
        for (int o = 16; o; o >>= 1) x += __shfl_xor_sync(0xffffffffu, x, o);
        if (lane == 0) wred[warp * 4 + r] = x;
    }
    __syncthreads();
    if (t < 4) {
        float s = 0.f;
#pragma unroll
        for (int w = 0; w < 8; w++) s += wred[w * 4 + t];
        stats[t] = s;
    }
    __syncthreads();
}

__device__ __forceinline__ void bmax4(const float v[4], float* wred, float* stats, int t)
{
    int lane = t & 31, warp = t >> 5;
#pragma unroll
    for (int r = 0; r < 4; r++) {
        float x = v[r];
#pragma unroll
        for (int o = 16; o; o >>= 1) x = fmaxf(x, __shfl_xor_sync(0xffffffffu, x, o));
        if (lane == 0) wred[warp * 4 + r] = x;
    }
    __syncthreads();
    if (t < 4) {
        float s = -1e30f;
#pragma unroll
        for (int w = 0; w < 8; w++) s = fmaxf(s, wred[w * 4 + t]);
        stats[t] = s;
    }
    __syncthreads();
}

__device__ __forceinline__ void ln_apply(float acc[4],
                                         const float* __restrict__ g,
                                         const float* __restrict__ b,
                                         int t, float* wred, float* stats)
{
    int lane = t & 31, warp = t >> 5;
#pragma unroll
    for (int r = 0; r < 4; r++) {
        float s = acc[r], q = acc[r] * acc[r];
#pragma unroll
        for (int o = 16; o; o >>= 1) {
            s += __shfl_xor_sync(0xffffffffu, s, o);
            q += __shfl_xor_sync(0xffffffffu, q, o);
        }
        if (lane == 0) { wred[warp * 8 + r] = s; wred[warp * 8 + 4 + r] = q; }
    }
    __syncthreads();
    if (t < 4) {
        float s = 0.f, q = 0.f;
#pragma unroll
        for (int w = 0; w < 8; w++) { s += wred[w * 8 + t]; q += wred[w * 8 + 4 + t]; }
        float mean = s * (1.f / 256.f);
        float var  = q * (1.f / 256.f) - mean * mean;
        stats[t]     = mean;
        stats[4 + t] = rsqrtf(var + 1e-5f);
    }
    __syncthreads();
    float gg = g[t], bb = b[t];
#pragma unroll
    for (int r = 0; r < 4; r++)
        acc[r] = (acc[r] - stats[r]) * stats[4 + r] * gg + bb;
}

// smem: xsA 1024 | xsB 1024 | ctx 1024 | sc 6400 | wred 64 | stats 32
#define SM_FLOATS (1024 * 3 + 6400 + 64 + 32)

__global__ __launch_bounds__(256, 2)
void mega_kernel(const float* __restrict__ mf, const float* __restrict__ regtab,
                 const int* __restrict__ rid,
                 const float* __restrict__ ew1, const float* __restrict__ eb1,
                 const float* __restrict__ l1g, const float* __restrict__ l1b,
                 const float* __restrict__ ew2, const float* __restrict__ eb2,
                 const float* __restrict__ l2g, const float* __restrict__ l2b,
                 const float* __restrict__ ew3, const float* __restrict__ eb3,
                 const float* __restrict__ gw1, const float* __restrict__ gb1,
                 const float* __restrict__ gw2, const float* __restrict__ gb2,
                 const float* __restrict__ gw3, const float* __restrict__ gb3,
                 const float* __restrict__ wq,  const float* __restrict__ bq,
                 const float* __restrict__ wo,  const float* __restrict__ bo,
                 const float* __restrict__ meT, const float* __restrict__ kT,
                 const float* __restrict__ v,   const float* __restrict__ mp,
                 float* __restrict__ out_pred, float* __restrict__ out_w,
                 float* __restrict__ divp, float* __restrict__ out_div)
{
    extern __shared__ float sm[];
    float* xsA   = sm;
    float* xsB   = xsA + 1024;
    float* ctxs  = xsB + 1024;
    float* sc    = ctxs + 1024;
    float* wred  = sc + 6400;
    float* stats = wred + 64;
    __shared__ int lastFlag;

    const int t  = threadIdx.x;
    const int b0 = blockIdx.x * 4;
    const bool s2 = (t < 144);

    if (t < 160) {
#pragma unroll
        for (int r = 0; r < 4; r++) {
            float x = (t < 128) ? mf[(b0 + r) * 128 + t]
                                : regtab[rid[b0 + r] * 32 + (t - 128)];
            xsA[t * 4 + r] = x;
        }
    }
    __syncthreads();

    float acc[4]; ull a2[2];

    // ---- enc1: K=160, LN, GELU ----
    set_bias2(a2, eb1[t]);
    gemm_col<160>(ew1, xsA, a2, t);
    unpack4(a2, acc);
    ln_apply(acc, l1g, l1b, t, wred, stats);
#pragma unroll
    for (int r = 0; r < 4; r++) acc[r] = gelu_exact(acc[r]);
    store_x(xsB, t, acc);
    __syncthreads();

    // ---- enc2 ----
    set_bias2(a2, eb2[t]);
    gemm_col<256>(ew2, xsB, a2, t);
    unpack4(a2, acc);
    ln_apply(acc, l2g, l2b, t, wred, stats);
#pragma unroll
    for (int r = 0; r < 4; r++) acc[r] = gelu_exact(acc[r]);
    store_x(xsA, t, acc);
    __syncthreads();

    // ---- enc3 -> ctx ----
    set_bias2(a2, eb3[t]);
    gemm_col<256>(ew3, xsA, a2, t);
    unpack4(a2, acc);
    store_x(ctxs, t, acc);
    __syncthreads();

    // ---- wg1 ----
    set_bias2(a2, gb1[t]);
    gemm_col<256>(gw1, ctxs, a2, t);
    unpack4(a2, acc);
#pragma unroll
    for (int r = 0; r < 4; r++) acc[r] = gelu_exact(acc[r]);
    store_x(xsB, t, acc);
    __syncthreads();

    // ---- wg2 ----
    set_bias2(a2, gb2[t]);
    gemm_col<256>(gw2, xsB, a2, t);
    unpack4(a2, acc);
#pragma unroll
    for (int r = 0; r < 4; r++) acc[r] = gelu_exact(acc[r]);
    store_x(xsA, t, acc);
    __syncthreads();

    // ---- wg3 -> base (kept in registers) ----
    float baseA[4], baseB[4];
    {
        ull aA[2] = {0, 0}, aB[2] = {0, 0};
        gemm_col400<256>(gw3, xsA, aA, aB, t, s2);
        unpack4(aA, baseA); unpack4(aB, baseB);
        float b1v = gb3[t], b2v = s2 ? gb3[t + 256] : 0.f;
#pragma unroll
        for (int r = 0; r < 4; r++) { baseA[r] += b1v; baseB[r] += b2v; }
    }

    // ---- q = ctx@wq + bq ----
    set_bias2(a2, bq[t]);
    gemm_col<256>(wq, ctxs, a2, t);
    unpack4(a2, acc);
    store_x(xsB, t, acc);
    __syncthreads();

    // ---- scores per head -> sc[h][m][r] ----
#pragma unroll
    for (int h = 0; h < 4; h++) {
        ull aA[2] = {0, 0}, aB[2] = {0, 0};
        gemm_col400<64>(kT + h * 64 * 400, xsB + h * 64 * 4, aA, aB, t, s2);
        float sA[4], sB[4];
        unpack4(aA, sA); unpack4(aB, sB);
        *(float4*)&sc[(h * 400 + t) * 4] =
            make_float4(sA[0]*0.125f, sA[1]*0.125f, sA[2]*0.125f, sA[3]*0.125f);
        if (s2)
            *(float4*)&sc[(h * 400 + t + 256) * 4] =
                make_float4(sB[0]*0.125f, sB[1]*0.125f, sB[2]*0.125f, sB[3]*0.125f);
    }
    __syncthreads();

    // ---- softmax over m for each (h, r): 16 pairs, warp each ----
    {
        int warp = t >> 5, lane = t & 31;
        for (int p = warp; p < 16; p += 8) {
            int h = p >> 2, r = p & 3;
            float* base = sc + h * 400 * 4 + r;
            float mx = -1e30f;
            for (int m = lane; m < 400; m += 32) mx = fmaxf(mx, base[m * 4]);
#pragma unroll
            for (int o = 16; o; o >>= 1) mx = fmaxf(mx, __shfl_xor_sync(0xffffffffu, mx, o));
            float s = 0.f;
            for (int m = lane; m < 400; m += 32) {
                float e = expf(base[m * 4] - mx);
                base[m * 4] = e;
                s += e;
            }
#pragma unroll
            for (int o = 16; o; o >>= 1) s += __shfl_xor_sync(0xffffffffu, s, o);
            float inv = 1.f / s;
            for (int m = lane; m < 400; m += 32) base[m * 4] *= inv;
        }
    }
    __syncthreads();

    // ---- att[r][t] = sum_m a[h(t)][r][m] * v[m][t] ----
    { ull z[2] = {0, 0};
      gemm_col<400>(v, sc + (t >> 6) * 400 * 4, z, t);
      unpack4(z, acc); }
    store_x(xsA, t, acc);
    __syncthreads();

    // ---- attended = att@wo + bo ----
    set_bias2(a2, bo[t]);
    gemm_col<256>(wo, xsA, a2, t);
    unpack4(a2, acc);
    store_x(xsB, t, acc);
    __syncthreads();

    // ---- attention_weights = attended @ me^T ----
    float awA[4], awB[4];
    {
        ull aA[2] = {0, 0}, aB[2] = {0, 0};
        gemm_col400<256>(meT, xsB, aA, aB, t, s2);
        unpack4(aA, awA); unpack4(aB, awB);
    }

    // ---- combine: softmax -> clip -> renorm -> w, prediction, diversity ----
    float lA[4], lB[4], m4[4];
#pragma unroll
    for (int r = 0; r < 4; r++) {
        lA[r] = baseA[r] + 0.5f * awA[r];
        lB[r] = s2 ? (baseB[r] + 0.5f * awB[r]) : -1e30f;
        m4[r] = fmaxf(lA[r], lB[r]);
    }
    bmax4(m4, wred, stats, t);
    float eA[4], eB[4];
#pragma unroll
    for (int r = 0; r < 4; r++) {
        float mx = stats[r];
        eA[r] = expf(lA[r] - mx);
        eB[r] = s2 ? expf(lB[r] - mx) : 0.f;
        m4[r] = eA[r] + eB[r];
    }
    bsum4(m4, wred, stats, t);
    float wA[4], wB[4];
#pragma unroll
    for (int r = 0; r < 4; r++) {
        float inv = 1.f / stats[r];
        wA[r] = fmaxf(eA[r] * inv, 0.001f);
        wB[r] = s2 ? fmaxf(eB[r] * inv, 0.001f) : 0.f;
        m4[r] = wA[r] + wB[r];
    }
    bsum4(m4, wred, stats, t);

    float p0[4], p1[4], p2[4], sx[4], sy[4], sz[4], tt[4];
#pragma unroll
    for (int r = 0; r < 4; r++) {
        float inv2 = 1.f / stats[r];
        wA[r] *= inv2;
        out_w[(size_t)(b0 + r) * 400 + t] = wA[r];
        const float* q1 = mp + ((size_t)(b0 + r) * 400 + t) * 3;
        float x0 = q1[0], x1 = q1[1], x2 = q1[2];
        float n2 = x0 * x0 + x1 * x1 + x2 * x2;
        float invn = 1.f / fmaxf(sqrtf(n2), 1e-12f);
        p0[r] = wA[r] * x0; p1[r] = wA[r] * x1; p2[r] = wA[r] * x2;
        sx[r] = x0 * invn;  sy[r] = x1 * invn;  sz[r] = x2 * invn;
        tt[r] = n2 * invn * invn;
        if (s2) {
            wB[r] *= inv2;
            out_w[(size_t)(b0 + r) * 400 + t + 256] = wB[r];
            const float* q2 = mp + ((size_t)(b0 + r) * 400 + t + 256) * 3;
            float y0 = q2[0], y1 = q2[1], y2 = q2[2];
            float nn = y0 * y0 + y1 * y1 + y2 * y2;
            float iv = 1.f / fmaxf(sqrtf(nn), 1e-12f);
            p0[r] += wB[r] * y0; p1[r] += wB[r] * y1; p2[r] += wB[r] * y2;
            sx[r] += y0 * iv;    sy[r] += y1 * iv;    sz[r] += y2 * iv;
            tt[r] += nn * iv * iv;
        }
    }
    bsum4(p0, wred, stats, t); float P0 = stats[t & 3];
    bsum4(p1, wred, stats, t); float P1 = stats[t & 3];
    bsum4(p2, wred, stats, t); float P2 = stats[t & 3];
    bsum4(sx, wred, stats, t); float SX = stats[t & 3];
    bsum4(sy, wred, stats, t); float SY = stats[t & 3];
    bsum4(sz, wred, stats, t); float SZ = stats[t & 3];
    bsum4(tt, wred, stats, t); float TT = stats[t & 3];
    if (t < 4) {
        out_pred[(b0 + t) * 3 + 0] = P0;
        out_pred[(b0 + t) * 3 + 1] = P1;
        out_pred[(b0 + t) * 3 + 2] = P2;
        divp[b0 + t] = SX * SX + SY * SY + SZ * SZ - TT;
    }

    // ---- last-block deterministic final reduction ----
    __syncthreads();
    if (t == 0) {
        __threadfence();
        int c = atomicAdd(&g_cnt, 1);
        lastFlag = (c == (int)gridDim.x - 1);
    }
    __syncthreads();
    if (lastFlag) {
        float s = 0.f;
        for (int i = t; i < 1024; i += 256) s += divp[i];
        int lane = t & 31, warp = t >> 5;
#pragma unroll
        for (int o = 16; o; o >>= 1) s += __shfl_xor_sync(0xffffffffu, s, o);
        if (lane == 0) wred[warp] = s;
        __syncthreads();
        if (t == 0) {
            float tot = 0.f;
#pragma unroll
            for (int w = 0; w < 8; w++) tot += wred[w];
            out_div[0] = tot / (1024.0f * 400.0f * 399.0f) * 0.1f;
            g_cnt = 0;
        }
    }
}

// =================================================================
extern "C" void kernel_launch(void* const* d_in, const int* in_sizes, int n_in,
                              void* d_out, int out_size)
{
    const float* mf     = (const float*)d_in[0];
    const float* mp     = (const float*)d_in[1];
    const float* regtab = (const float*)d_in[2];
    const float* enc_w1 = (const float*)d_in[3];
    const float* enc_b1 = (const float*)d_in[4];
    const float* ln1g   = (const float*)d_in[5];
    const float* ln1b   = (const float*)d_in[6];
    const float* enc_w2 = (const float*)d_in[7];
    const float* enc_b2 = (const float*)d_in[8];
    const float* ln2g   = (const float*)d_in[9];
    const float* ln2b   = (const float*)d_in[10];
    const float* enc_w3 = (const float*)d_in[11];
    const float* enc_b3 = (const float*)d_in[12];
    const float* wg_w1  = (const float*)d_in[13];
    const float* wg_b1  = (const float*)d_in[14];
    const float* wg_w2  = (const float*)d_in[15];
    const float* wg_b2  = (const float*)d_in[16];
    const float* wg_w3  = (const float*)d_in[17];
    const float* wg_b3  = (const float*)d_in[18];
    const float* memb   = (const float*)d_in[19];
    const float* proj_w = (const float*)d_in[20];
    const float* proj_b = (const float*)d_in[21];
    const float* wq     = (const float*)d_in[22];
    const float* bq     = (const float*)d_in[23];
    const float* wk     = (const float*)d_in[24];
    const float* bk     = (const float*)d_in[25];
    const float* wv     = (const float*)d_in[26];
    const float* bv     = (const float*)d_in[27];
    const float* wo     = (const float*)d_in[28];
    const float* bo     = (const float*)d_in[29];
    const int*   rid    = (const int*)d_in[30];
    float* out = (float*)d_out;

    float *meT, *kT, *v, *divp;
    cudaGetSymbolAddress((void**)&meT,  g_meT);
    cudaGetSymbolAddress((void**)&kT,   g_kT);
    cudaGetSymbolAddress((void**)&v,    g_v);
    cudaGetSymbolAddress((void**)&divp, g_div);

    const int smem_bytes = SM_FLOATS * (int)sizeof(float);
    cudaFuncSetAttribute(mega_kernel, cudaFuncAttributeMaxDynamicSharedMemorySize,
                         smem_bytes);

    prep_kernel<<<dim3(100, 2), 256>>>(memb, proj_w, proj_b, wk, bk, wv, bv,
                                       meT, kT, v);

    mega_kernel<<<256, 256, smem_bytes>>>(
        mf, regtab, rid,
        enc_w1, enc_b1, ln1g, ln1b,
        enc_w2, enc_b2, ln2g, ln2b,
        enc_w3, enc_b3,
        wg_w1, wg_b1, wg_w2, wg_b2, wg_w3, wg_b3,
        wq, bq, wo, bo,
        meT, kT, v, mp,
        out, out + 3072, divp, out + 412672);
}